// round 2
// baseline (speedup 1.0000x reference)
#include <cuda_runtime.h>
#include <cuda_bf16.h>

#define HID   2048
#define NHEADS 16
#define HD    128
#define BATCH 2
#define SEQ   2048
#define MTOT  (BATCH * SEQ)   // 4096

// Scratch (static device allocations are allowed; cudaMalloc is not)
__device__ float g_q[(size_t)BATCH * NHEADS * SEQ * HD];    // 32 MB
__device__ float g_k[(size_t)BATCH * NHEADS * SEQ * HD];    // 32 MB
__device__ float g_v[(size_t)BATCH * NHEADS * SEQ * HD];    // 32 MB
__device__ float g_attn[(size_t)MTOT * HID];                // 32 MB

// ---------------------------------------------------------------------------
// SGEMM: C[M,N] = A[M,K] @ B[K,N] + bias, M=4096, N=K=2048.
// 128x128 block tile, BK=16, 256 threads, 8x8 per-thread micro-tile.
// split==1: scatter output into (b, h, s, d) head-split layout for attention.
// ---------------------------------------------------------------------------
__global__ __launch_bounds__(256) void sgemm_bias_kernel(
    const float* __restrict__ A, const float* __restrict__ B,
    const float* __restrict__ bias, float* __restrict__ C, int split)
{
    const int K = HID, N = HID;
    __shared__ float As[16][132];   // stored transposed: As[k][m]
    __shared__ float Bs[16][132];

    const int tid = threadIdx.x;
    const int tx = tid & 15, ty = tid >> 4;
    const int bm = blockIdx.y * 128, bn = blockIdx.x * 128;

    float acc[8][8];
#pragma unroll
    for (int i = 0; i < 8; i++)
#pragma unroll
        for (int j = 0; j < 8; j++) acc[i][j] = 0.f;

    const int ar = tid >> 2, ac4 = (tid & 3) * 4;  // A tile: 128 rows x 4 float4
    const int br = tid >> 5, bc = (tid & 31) * 4;  // B tile: 16 rows x 32 float4

    for (int k0 = 0; k0 < K; k0 += 16) {
        float4 a0 = *(const float4*)(A + (size_t)(bm + ar) * K + k0 + ac4);
        float4 a1 = *(const float4*)(A + (size_t)(bm + ar + 64) * K + k0 + ac4);
        float4 b0 = *(const float4*)(B + (size_t)(k0 + br) * N + bn + bc);
        float4 b1 = *(const float4*)(B + (size_t)(k0 + br + 8) * N + bn + bc);

        As[ac4 + 0][ar] = a0.x;  As[ac4 + 1][ar] = a0.y;
        As[ac4 + 2][ar] = a0.z;  As[ac4 + 3][ar] = a0.w;
        As[ac4 + 0][ar + 64] = a1.x;  As[ac4 + 1][ar + 64] = a1.y;
        As[ac4 + 2][ar + 64] = a1.z;  As[ac4 + 3][ar + 64] = a1.w;
        *(float4*)&Bs[br][bc]     = b0;
        *(float4*)&Bs[br + 8][bc] = b1;
        __syncthreads();

#pragma unroll
        for (int kk = 0; kk < 16; kk++) {
            float ra[8], rb[8];
            *(float4*)&ra[0] = *(const float4*)&As[kk][ty * 8];
            *(float4*)&ra[4] = *(const float4*)&As[kk][ty * 8 + 4];
            *(float4*)&rb[0] = *(const float4*)&Bs[kk][tx * 8];
            *(float4*)&rb[4] = *(const float4*)&Bs[kk][tx * 8 + 4];
#pragma unroll
            for (int i = 0; i < 8; i++)
#pragma unroll
                for (int j = 0; j < 8; j++)
                    acc[i][j] = fmaf(ra[i], rb[j], acc[i][j]);
        }
        __syncthreads();
    }

#pragma unroll
    for (int i = 0; i < 8; i++) {
        const int row = bm + ty * 8 + i;
#pragma unroll
        for (int j = 0; j < 8; j++) {
            const int col = bn + tx * 8 + j;
            const float v = acc[i][j] + bias[col];
            if (split) {
                const int b = row >> 11, s = row & 2047;
                const int h = col >> 7, d = col & 127;
                C[(((size_t)(b * NHEADS + h)) * SEQ + s) * HD + d] = v;
            } else {
                C[(size_t)row * N + col] = v;
            }
        }
    }
}

// ---------------------------------------------------------------------------
// Flash-style attention: per (b,h), 64-row Q tiles vs 64-row K/V tiles,
// online softmax, fp32. 256 threads (16x16), each thread 4x4 of score tile,
// 4x8 of output tile. Dynamic smem: Qs/Ks/Vs 64x132, Ps 64x68.
// ---------------------------------------------------------------------------
#define ATTN_SMEM_FLOATS (3 * 64 * 132 + 64 * 68)
#define ATTN_SMEM_BYTES  (ATTN_SMEM_FLOATS * 4)

__global__ __launch_bounds__(256) void attn_kernel(
    const float* __restrict__ Q, const float* __restrict__ K,
    const float* __restrict__ V, float* __restrict__ O)
{
    extern __shared__ float sm[];
    float* Qs = sm;                 // [64][132]
    float* Ks = sm + 64 * 132;      // [64][132]
    float* Vs = sm + 2 * 64 * 132;  // [64][132]
    float* Ps = sm + 3 * 64 * 132;  // [64][68]

    const int tid = threadIdx.x;
    const int tx = tid & 15, ty = tid >> 4;
    const int bh = blockIdx.y;      // b*16 + h
    const int qt = blockIdx.x;      // q tile index
    const float scale = 0.08838834764831845f;  // 1/sqrt(128)

    // Load Q tile (pre-scaled)
    const float* qg = Q + ((size_t)bh * SEQ + qt * 64) * HD;
    for (int idx = tid; idx < 64 * 32; idx += 256) {
        const int r = idx >> 5, c = (idx & 31) * 4;
        float4 v = *(const float4*)(qg + r * HD + c);
        v.x *= scale; v.y *= scale; v.z *= scale; v.w *= scale;
        *(float4*)&Qs[r * 132 + c] = v;
    }

    float m[4], l[4], o[4][8];
#pragma unroll
    for (int i = 0; i < 4; i++) {
        m[i] = -1e30f; l[i] = 0.f;
#pragma unroll
        for (int c = 0; c < 8; c++) o[i][c] = 0.f;
    }

    for (int j0 = 0; j0 < SEQ; j0 += 64) {
        const float* kg = K + ((size_t)bh * SEQ + j0) * HD;
        const float* vg = V + ((size_t)bh * SEQ + j0) * HD;
        for (int idx = tid; idx < 64 * 32; idx += 256) {
            const int r = idx >> 5, c = (idx & 31) * 4;
            *(float4*)&Ks[r * 132 + c] = *(const float4*)(kg + r * HD + c);
            *(float4*)&Vs[r * 132 + c] = *(const float4*)(vg + r * HD + c);
        }
        __syncthreads();

        // Scores s[i][j] = (Q*scale) . K
        float s[4][4];
#pragma unroll
        for (int i = 0; i < 4; i++)
#pragma unroll
            for (int j = 0; j < 4; j++) s[i][j] = 0.f;

#pragma unroll 8
        for (int d4 = 0; d4 < 32; d4++) {
            float4 q4[4], k4[4];
#pragma unroll
            for (int i = 0; i < 4; i++)
                q4[i] = *(const float4*)&Qs[(ty * 4 + i) * 132 + d4 * 4];
#pragma unroll
            for (int j = 0; j < 4; j++)
                k4[j] = *(const float4*)&Ks[(tx * 4 + j) * 132 + d4 * 4];
#pragma unroll
            for (int i = 0; i < 4; i++)
#pragma unroll
                for (int j = 0; j < 4; j++) {
                    s[i][j] = fmaf(q4[i].x, k4[j].x, s[i][j]);
                    s[i][j] = fmaf(q4[i].y, k4[j].y, s[i][j]);
                    s[i][j] = fmaf(q4[i].z, k4[j].z, s[i][j]);
                    s[i][j] = fmaf(q4[i].w, k4[j].w, s[i][j]);
                }
        }

        // Online softmax (row reductions across tx = lanes 0..15 of half-warp)
#pragma unroll
        for (int i = 0; i < 4; i++) {
            float mx = fmaxf(fmaxf(s[i][0], s[i][1]), fmaxf(s[i][2], s[i][3]));
#pragma unroll
            for (int off = 8; off >= 1; off >>= 1)
                mx = fmaxf(mx, __shfl_xor_sync(0xffffffffu, mx, off));
            const float mnew = fmaxf(m[i], mx);
            const float corr = __expf(m[i] - mnew);
            m[i] = mnew;
            float rs = 0.f;
#pragma unroll
            for (int j = 0; j < 4; j++) {
                const float p = __expf(s[i][j] - mnew);
                s[i][j] = p;
                rs += p;
            }
#pragma unroll
            for (int off = 8; off >= 1; off >>= 1)
                rs += __shfl_xor_sync(0xffffffffu, rs, off);
            l[i] = l[i] * corr + rs;
#pragma unroll
            for (int c = 0; c < 8; c++) o[i][c] *= corr;
            *(float4*)&Ps[(ty * 4 + i) * 68 + tx * 4] =
                make_float4(s[i][0], s[i][1], s[i][2], s[i][3]);
        }
        __syncthreads();

        // O += P @ V
#pragma unroll 4
        for (int kv = 0; kv < 64; kv++) {
            float p[4];
#pragma unroll
            for (int i = 0; i < 4; i++) p[i] = Ps[(ty * 4 + i) * 68 + kv];
            const float4 va = *(const float4*)&Vs[kv * 132 + tx * 4];
            const float4 vb = *(const float4*)&Vs[kv * 132 + 64 + tx * 4];
#pragma unroll
            for (int i = 0; i < 4; i++) {
                o[i][0] = fmaf(p[i], va.x, o[i][0]);
                o[i][1] = fmaf(p[i], va.y, o[i][1]);
                o[i][2] = fmaf(p[i], va.z, o[i][2]);
                o[i][3] = fmaf(p[i], va.w, o[i][3]);
                o[i][4] = fmaf(p[i], vb.x, o[i][4]);
                o[i][5] = fmaf(p[i], vb.y, o[i][5]);
                o[i][6] = fmaf(p[i], vb.z, o[i][6]);
                o[i][7] = fmaf(p[i], vb.w, o[i][7]);
            }
        }
        __syncthreads();
    }

    // Epilogue: normalize and write to merged-head layout [B*S, HID]
    const int b = bh >> 4, h = bh & 15;
#pragma unroll
    for (int i = 0; i < 4; i++) {
        const int srow = qt * 64 + ty * 4 + i;
        const float inv = 1.0f / l[i];
        float* op = O + ((size_t)(b * SEQ) + srow) * HID + h * HD;
        *(float4*)(op + tx * 4) =
            make_float4(o[i][0] * inv, o[i][1] * inv, o[i][2] * inv, o[i][3] * inv);
        *(float4*)(op + 64 + tx * 4) =
            make_float4(o[i][4] * inv, o[i][5] * inv, o[i][6] * inv, o[i][7] * inv);
    }
}

// ---------------------------------------------------------------------------
extern "C" void kernel_launch(void* const* d_in, const int* in_sizes, int n_in,
                              void* d_out, int out_size) {
    const float* X  = (const float*)d_in[0];
    const float* Wq = (const float*)d_in[1];
    const float* bq = (const float*)d_in[2];
    const float* Wk = (const float*)d_in[3];
    const float* bk = (const float*)d_in[4];
    const float* Wv = (const float*)d_in[5];
    const float* bv = (const float*)d_in[6];
    const float* Wo = (const float*)d_in[7];
    const float* bo = (const float*)d_in[8];
    float* out = (float*)d_out;

    float *q, *k, *v, *attn;
    cudaGetSymbolAddress((void**)&q, g_q);
    cudaGetSymbolAddress((void**)&k, g_k);
    cudaGetSymbolAddress((void**)&v, g_v);
    cudaGetSymbolAddress((void**)&attn, g_attn);

    cudaFuncSetAttribute(attn_kernel,
                         cudaFuncAttributeMaxDynamicSharedMemorySize,
                         ATTN_SMEM_BYTES);

    const dim3 gg(HID / 128, MTOT / 128);   // (16, 32)
    const dim3 blk(256);

    sgemm_bias_kernel<<<gg, blk>>>(X, Wq, bq, q, 1);
    sgemm_bias_kernel<<<gg, blk>>>(X, Wk, bk, k, 1);
    sgemm_bias_kernel<<<gg, blk>>>(X, Wv, bv, v, 1);
    attn_kernel<<<dim3(SEQ / 64, BATCH * NHEADS), blk, ATTN_SMEM_BYTES>>>(q, k, v, attn);
    sgemm_bias_kernel<<<gg, blk>>>(attn, Wo, bo, out, 0);
}

// round 5
// speedup vs baseline: 1.4240x; 1.4240x over previous
#include <cuda_runtime.h>
#include <cuda_bf16.h>
#include <cstdint>

#define HID    2048
#define NHEADS 16
#define HD     128
#define BATCH  2
#define SEQ    2048
#define MTOT   (BATCH * SEQ)   // 4096

// ---------------------------------------------------------------------------
// Scratch (static device arrays; no cudaMalloc anywhere)
// ---------------------------------------------------------------------------
__device__ float g_q[(size_t)BATCH * NHEADS * SEQ * HD];
__device__ float g_k[(size_t)BATCH * NHEADS * SEQ * HD];
__device__ float g_v[(size_t)BATCH * NHEADS * SEQ * HD];
__device__ float g_attn[(size_t)MTOT * HID];
__device__ __nv_bfloat16 g_xhi[(size_t)MTOT * HID];
__device__ __nv_bfloat16 g_xlo[(size_t)MTOT * HID];
__device__ __nv_bfloat16 g_ahi[(size_t)MTOT * HID];
__device__ __nv_bfloat16 g_alo[(size_t)MTOT * HID];
__device__ __nv_bfloat16 g_whi[4][(size_t)HID * HID];   // [N][K] transposed
__device__ __nv_bfloat16 g_wlo[4][(size_t)HID * HID];

// ---------------------------------------------------------------------------
// PTX helpers — ONLY base-target-safe instructions (no tcgen05 on compute_103)
// ---------------------------------------------------------------------------
static __device__ __forceinline__ uint32_t smem_u32(const void* p) {
    return (uint32_t)__cvta_generic_to_shared(p);
}

#define CP_ASYNC16(dst, src) \
    asm volatile("cp.async.cg.shared.global [%0], [%1], 16;" \
        :: "r"(dst), "l"(src) : "memory")
#define CP_COMMIT() asm volatile("cp.async.commit_group;" ::: "memory")
#define CP_WAIT_1() asm volatile("cp.async.wait_group 1;" ::: "memory")
#define CP_WAIT_0() asm volatile("cp.async.wait_group 0;" ::: "memory")

#define LDSM_X4(r0, r1, r2, r3, addr) \
    asm volatile("ldmatrix.sync.aligned.m8n8.x4.shared.b16 {%0,%1,%2,%3}, [%4];" \
        : "=r"(r0), "=r"(r1), "=r"(r2), "=r"(r3) : "r"(addr))

// mma m16n8k16 row.col bf16 -> f32
#define MMA_BF16(c, a, b0, b1) \
    asm volatile("mma.sync.aligned.m16n8k16.row.col.f32.bf16.bf16.f32 " \
        "{%0,%1,%2,%3}, {%4,%5,%6,%7}, {%8,%9}, {%0,%1,%2,%3};" \
        : "+f"((c)[0]), "+f"((c)[1]), "+f"((c)[2]), "+f"((c)[3]) \
        : "r"((a)[0]), "r"((a)[1]), "r"((a)[2]), "r"((a)[3]), "r"(b0), "r"(b1))

// ---------------------------------------------------------------------------
// Convert: fp32 -> (bf16 hi, bf16 lo), row-major, elementwise
// ---------------------------------------------------------------------------
__global__ __launch_bounds__(256) void convert_hilo_kernel(
    const float* __restrict__ X, __nv_bfloat16* __restrict__ hi,
    __nv_bfloat16* __restrict__ lo, int n4)
{
    int i = blockIdx.x * blockDim.x + threadIdx.x;
    if (i >= n4) return;
    float4 v = ((const float4*)X)[i];
    float xs[4] = {v.x, v.y, v.z, v.w};
    __align__(8) __nv_bfloat16 h[4], l[4];
#pragma unroll
    for (int j = 0; j < 4; ++j) {
        h[j] = __float2bfloat16(xs[j]);
        l[j] = __float2bfloat16(xs[j] - __bfloat162float(h[j]));
    }
    ((uint2*)hi)[i] = *(const uint2*)h;
    ((uint2*)lo)[i] = *(const uint2*)l;
}

// ---------------------------------------------------------------------------
// Convert + transpose: W fp32 [K,N] -> hi/lo bf16 [N,K]
// ---------------------------------------------------------------------------
__global__ __launch_bounds__(256) void convert_wt_kernel(
    const float* __restrict__ W, __nv_bfloat16* __restrict__ hi,
    __nv_bfloat16* __restrict__ lo)
{
    __shared__ float sm[64][65];
    const int k0 = blockIdx.y * 64, n0 = blockIdx.x * 64;
    const int tid = threadIdx.x;
#pragma unroll
    for (int i = 0; i < 4; ++i) {
        int id = tid + i * 256;
        int r = id >> 4, g = id & 15;
        float4 v = *(const float4*)(W + (size_t)(k0 + r) * HID + n0 + g * 4);
        sm[r][g * 4 + 0] = v.x; sm[r][g * 4 + 1] = v.y;
        sm[r][g * 4 + 2] = v.z; sm[r][g * 4 + 3] = v.w;
    }
    __syncthreads();
#pragma unroll
    for (int i = 0; i < 4; ++i) {
        int id = tid + i * 256;
        int r = id >> 4, g = id & 15;
        __align__(8) __nv_bfloat16 h[4], l[4];
#pragma unroll
        for (int j = 0; j < 4; ++j) {
            float x = sm[g * 4 + j][r];
            h[j] = __float2bfloat16(x);
            l[j] = __float2bfloat16(x - __bfloat162float(h[j]));
        }
        size_t off = (size_t)(n0 + r) * HID + k0 + g * 4;
        *(uint2*)(hi + off) = *(const uint2*)h;
        *(uint2*)(lo + off) = *(const uint2*)l;
    }
}

// ---------------------------------------------------------------------------
// 3xBF16 tensor-core GEMM via mma.sync: C[4096,2048] = A @ B^T + bias
//   A = (Ahi,Alo) bf16 [M,K] row-major; B = (Bhi,Blo) bf16 [N,K] row-major.
//   C = Ahi*Bhi + Ahi*Blo + Alo*Bhi  (fp32 accum; dropped lo*lo ~ 2^-16)
// CTA 128x128, BK=32, 8 warps (warp tile 64x32), cp.async double buffer.
// Smem rows padded to 80B -> conflict-free ldmatrix.
// split=1: scatter into (b,h,s,d) head-split layout.
// ---------------------------------------------------------------------------
#define BM 128
#define BN 128
#define BK 32
#define KT (HID / BK)          // 64
#define ROWB 80                // padded row bytes (32 bf16 + 8 pad)
#define TILE_B (128 * ROWB)    // 10240
#define STAGE_B (4 * TILE_B)   // 40960: Ahi, Alo, Bhi, Blo
#define GEMM_SMEM_BYTES (2 * STAGE_B)  // 81920

static __device__ __forceinline__ void load_stage(
    const __nv_bfloat16* __restrict__ Ahi, const __nv_bfloat16* __restrict__ Alo,
    const __nv_bfloat16* __restrict__ Bhi, const __nv_bfloat16* __restrict__ Blo,
    int bm, int bn, int k0, uint32_t s_base, int tid)
{
#pragma unroll
    for (int i = 0; i < 8; ++i) {
        const int mat = i >> 1;                 // 0:Ahi 1:Alo 2:Bhi 3:Blo
        const int idx = ((i & 1) << 8) + tid;   // 0..511
        const int row = idx >> 2;
        const int ch  = idx & 3;                // 16B chunk in row
        const int grow = (mat < 2 ? bm : bn) + row;
        const __nv_bfloat16* src =
            (mat == 0 ? Ahi : mat == 1 ? Alo : mat == 2 ? Bhi : Blo)
            + (size_t)grow * HID + k0 + ch * 8;
        const uint32_t dst = s_base + mat * TILE_B + row * ROWB + ch * 16;
        CP_ASYNC16(dst, src);
    }
}

__global__ __launch_bounds__(256) void gemm_bf16x3_kernel(
    const __nv_bfloat16* __restrict__ Ahi, const __nv_bfloat16* __restrict__ Alo,
    const __nv_bfloat16* __restrict__ Bhi, const __nv_bfloat16* __restrict__ Blo,
    const float* __restrict__ bias, float* __restrict__ C, int split)
{
    extern __shared__ char smc[];
    const uint32_t s_base = smem_u32(smc);
    const int tid  = threadIdx.x;
    const int wid  = tid >> 5, lane = tid & 31;
    const int wm   = wid & 1, wn = wid >> 1;    // 2 x 4 warp grid
    const int m_base = wm * 64, n_base = wn * 32;
    const int bm = blockIdx.y * BM, bn = blockIdx.x * BN;

    float c[4][4][4];
#pragma unroll
    for (int i = 0; i < 4; ++i)
#pragma unroll
        for (int j = 0; j < 4; ++j)
#pragma unroll
            for (int r = 0; r < 4; ++r) c[i][j][r] = 0.f;

    // ldmatrix address components
    const int a_r = lane & 15;                      // A row within 16
    const int a_c = (lane & 16) ? 8 : 0;            // A col sel (k)
    const int b_r = (lane & 7) + ((lane & 16) ? 8 : 0);  // B row (n) within 16
    const int b_c = (lane & 8) ? 8 : 0;             // B col sel (k)

    load_stage(Ahi, Alo, Bhi, Blo, bm, bn, 0, s_base, tid);
    CP_COMMIT();

    for (int t = 0; t < KT; ++t) {
        if (t + 1 < KT) {
            load_stage(Ahi, Alo, Bhi, Blo, bm, bn, (t + 1) * BK,
                       s_base + ((t + 1) & 1) * STAGE_B, tid);
            CP_COMMIT();
            CP_WAIT_1();
        } else {
            CP_WAIT_0();
        }
        __syncthreads();

        const uint32_t sb  = s_base + (t & 1) * STAGE_B;
        const uint32_t sAh = sb;
        const uint32_t sAl = sb + TILE_B;
        const uint32_t sBh = sb + 2 * TILE_B;
        const uint32_t sBl = sb + 3 * TILE_B;

#pragma unroll
        for (int ks = 0; ks < 2; ++ks) {
            const int kofs = ks * 16;
            uint32_t ah[4][4], al[4][4], bh[2][4], bl[2][4];
#pragma unroll
            for (int mf = 0; mf < 4; ++mf) {
                const uint32_t ra = (uint32_t)((m_base + mf * 16 + a_r) * ROWB
                                               + (kofs + a_c) * 2);
                LDSM_X4(ah[mf][0], ah[mf][1], ah[mf][2], ah[mf][3], sAh + ra);
                LDSM_X4(al[mf][0], al[mf][1], al[mf][2], al[mf][3], sAl + ra);
            }
#pragma unroll
            for (int nb = 0; nb < 2; ++nb) {
                const uint32_t rb = (uint32_t)((n_base + nb * 16 + b_r) * ROWB
                                               + (kofs + b_c) * 2);
                LDSM_X4(bh[nb][0], bh[nb][1], bh[nb][2], bh[nb][3], sBh + rb);
                LDSM_X4(bl[nb][0], bl[nb][1], bl[nb][2], bl[nb][3], sBl + rb);
            }
#pragma unroll
            for (int mf = 0; mf < 4; ++mf)
#pragma unroll
                for (int nf = 0; nf < 4; ++nf) {
                    const int nb = nf >> 1, sel = (nf & 1) * 2;
                    MMA_BF16(c[mf][nf], ah[mf], bh[nb][sel], bh[nb][sel + 1]);
                    MMA_BF16(c[mf][nf], ah[mf], bl[nb][sel], bl[nb][sel + 1]);
                    MMA_BF16(c[mf][nf], al[mf], bh[nb][sel], bh[nb][sel + 1]);
                }
        }
        __syncthreads();
    }

    // Epilogue: C fragment: d0,d1 = C[g][2t..], d2,d3 = C[g+8][2t..]
    const int g = lane >> 2, t4 = lane & 3;
#pragma unroll
    for (int mf = 0; mf < 4; ++mf) {
#pragma unroll
        for (int nf = 0; nf < 4; ++nf) {
            const int cb = bn + n_base + nf * 8 + t4 * 2;
            const float b0 = bias[cb], b1 = bias[cb + 1];
#pragma unroll
            for (int half = 0; half < 2; ++half) {
                const int row = bm + m_base + mf * 16 + g + half * 8;
                float2 v;
                v.x = c[mf][nf][half * 2 + 0] + b0;
                v.y = c[mf][nf][half * 2 + 1] + b1;
                float* dst;
                if (split) {
                    const int b = row >> 11, s = row & 2047;
                    const int h = cb >> 7, d = cb & 127;
                    dst = C + (((size_t)(b * NHEADS + h)) * SEQ + s) * HD + d;
                } else {
                    dst = C + (size_t)row * HID + cb;
                }
                *(float2*)dst = v;
            }
        }
    }
}

// ---------------------------------------------------------------------------
// Flash-style attention (unchanged, known-good): fp32, 64-row Q/KV tiles
// ---------------------------------------------------------------------------
#define ATTN_SMEM_FLOATS (3 * 64 * 132 + 64 * 68)
#define ATTN_SMEM_BYTES  (ATTN_SMEM_FLOATS * 4)

__global__ __launch_bounds__(256) void attn_kernel(
    const float* __restrict__ Q, const float* __restrict__ K,
    const float* __restrict__ V, float* __restrict__ O)
{
    extern __shared__ float smf[];
    float* Qs = smf;
    float* Ks = smf + 64 * 132;
    float* Vs = smf + 2 * 64 * 132;
    float* Ps = smf + 3 * 64 * 132;

    const int tid = threadIdx.x;
    const int tx = tid & 15, ty = tid >> 4;
    const int bh = blockIdx.y;
    const int qt = blockIdx.x;
    const float scale = 0.08838834764831845f;

    const float* qg = Q + ((size_t)bh * SEQ + qt * 64) * HD;
    for (int idx = tid; idx < 64 * 32; idx += 256) {
        const int r = idx >> 5, c = (idx & 31) * 4;
        float4 v = *(const float4*)(qg + r * HD + c);
        v.x *= scale; v.y *= scale; v.z *= scale; v.w *= scale;
        *(float4*)&Qs[r * 132 + c] = v;
    }

    float m[4], l[4], o[4][8];
#pragma unroll
    for (int i = 0; i < 4; i++) {
        m[i] = -1e30f; l[i] = 0.f;
#pragma unroll
        for (int c = 0; c < 8; c++) o[i][c] = 0.f;
    }

    for (int j0 = 0; j0 < SEQ; j0 += 64) {
        const float* kg = K + ((size_t)bh * SEQ + j0) * HD;
        const float* vg = V + ((size_t)bh * SEQ + j0) * HD;
        for (int idx = tid; idx < 64 * 32; idx += 256) {
            const int r = idx >> 5, c = (idx & 31) * 4;
            *(float4*)&Ks[r * 132 + c] = *(const float4*)(kg + r * HD + c);
            *(float4*)&Vs[r * 132 + c] = *(const float4*)(vg + r * HD + c);
        }
        __syncthreads();

        float s[4][4];
#pragma unroll
        for (int i = 0; i < 4; i++)
#pragma unroll
            for (int j = 0; j < 4; j++) s[i][j] = 0.f;

#pragma unroll 8
        for (int d4 = 0; d4 < 32; d4++) {
            float4 q4[4], k4[4];
#pragma unroll
            for (int i = 0; i < 4; i++)
                q4[i] = *(const float4*)&Qs[(ty * 4 + i) * 132 + d4 * 4];
#pragma unroll
            for (int j = 0; j < 4; j++)
                k4[j] = *(const float4*)&Ks[(tx * 4 + j) * 132 + d4 * 4];
#pragma unroll
            for (int i = 0; i < 4; i++)
#pragma unroll
                for (int j = 0; j < 4; j++) {
                    s[i][j] = fmaf(q4[i].x, k4[j].x, s[i][j]);
                    s[i][j] = fmaf(q4[i].y, k4[j].y, s[i][j]);
                    s[i][j] = fmaf(q4[i].z, k4[j].z, s[i][j]);
                    s[i][j] = fmaf(q4[i].w, k4[j].w, s[i][j]);
                }
        }

#pragma unroll
        for (int i = 0; i < 4; i++) {
            float mx = fmaxf(fmaxf(s[i][0], s[i][1]), fmaxf(s[i][2], s[i][3]));
#pragma unroll
            for (int off = 8; off >= 1; off >>= 1)
                mx = fmaxf(mx, __shfl_xor_sync(0xffffffffu, mx, off));
            const float mnew = fmaxf(m[i], mx);
            const float corr = __expf(m[i] - mnew);
            m[i] = mnew;
            float rs = 0.f;
#pragma unroll
            for (int j = 0; j < 4; j++) {
                const float p = __expf(s[i][j] - mnew);
                s[i][j] = p;
                rs += p;
            }
#pragma unroll
            for (int off = 8; off >= 1; off >>= 1)
                rs += __shfl_xor_sync(0xffffffffu, rs, off);
            l[i] = l[i] * corr + rs;
#pragma unroll
            for (int c = 0; c < 8; c++) o[i][c] *= corr;
            *(float4*)&Ps[(ty * 4 + i) * 68 + tx * 4] =
                make_float4(s[i][0], s[i][1], s[i][2], s[i][3]);
        }
        __syncthreads();

#pragma unroll 4
        for (int kv = 0; kv < 64; kv++) {
            float p[4];
#pragma unroll
            for (int i = 0; i < 4; i++) p[i] = Ps[(ty * 4 + i) * 68 + kv];
            const float4 va = *(const float4*)&Vs[kv * 132 + tx * 4];
            const float4 vb = *(const float4*)&Vs[kv * 132 + 64 + tx * 4];
#pragma unroll
            for (int i = 0; i < 4; i++) {
                o[i][0] = fmaf(p[i], va.x, o[i][0]);
                o[i][1] = fmaf(p[i], va.y, o[i][1]);
                o[i][2] = fmaf(p[i], va.z, o[i][2]);
                o[i][3] = fmaf(p[i], va.w, o[i][3]);
                o[i][4] = fmaf(p[i], vb.x, o[i][4]);
                o[i][5] = fmaf(p[i], vb.y, o[i][5]);
                o[i][6] = fmaf(p[i], vb.z, o[i][6]);
                o[i][7] = fmaf(p[i], vb.w, o[i][7]);
            }
        }
        __syncthreads();
    }

    const int b = bh >> 4, h = bh & 15;
#pragma unroll
    for (int i = 0; i < 4; i++) {
        const int srow = qt * 64 + ty * 4 + i;
        const float inv = 1.0f / l[i];
        float* op = O + ((size_t)(b * SEQ) + srow) * HID + h * HD;
        *(float4*)(op + tx * 4) =
            make_float4(o[i][0] * inv, o[i][1] * inv, o[i][2] * inv, o[i][3] * inv);
        *(float4*)(op + 64 + tx * 4) =
            make_float4(o[i][4] * inv, o[i][5] * inv, o[i][6] * inv, o[i][7] * inv);
    }
}

// ---------------------------------------------------------------------------
extern "C" void kernel_launch(void* const* d_in, const int* in_sizes, int n_in,
                              void* d_out, int out_size) {
    const float* X  = (const float*)d_in[0];
    const float* Wq = (const float*)d_in[1];
    const float* bq = (const float*)d_in[2];
    const float* Wk = (const float*)d_in[3];
    const float* bk = (const float*)d_in[4];
    const float* Wv = (const float*)d_in[5];
    const float* bv = (const float*)d_in[6];
    const float* Wo = (const float*)d_in[7];
    const float* bo = (const float*)d_in[8];
    float* out = (float*)d_out;

    float *q, *k, *v, *attn;
    __nv_bfloat16 *xhi, *xlo, *ahi, *alo, *whi, *wlo;
    cudaGetSymbolAddress((void**)&q, g_q);
    cudaGetSymbolAddress((void**)&k, g_k);
    cudaGetSymbolAddress((void**)&v, g_v);
    cudaGetSymbolAddress((void**)&attn, g_attn);
    cudaGetSymbolAddress((void**)&xhi, g_xhi);
    cudaGetSymbolAddress((void**)&xlo, g_xlo);
    cudaGetSymbolAddress((void**)&ahi, g_ahi);
    cudaGetSymbolAddress((void**)&alo, g_alo);
    cudaGetSymbolAddress((void**)&whi, g_whi);
    cudaGetSymbolAddress((void**)&wlo, g_wlo);

    cudaFuncSetAttribute(gemm_bf16x3_kernel,
                         cudaFuncAttributeMaxDynamicSharedMemorySize, GEMM_SMEM_BYTES);
    cudaFuncSetAttribute(attn_kernel,
                         cudaFuncAttributeMaxDynamicSharedMemorySize, ATTN_SMEM_BYTES);

    const size_t WSZ = (size_t)HID * HID;
    const int n4 = MTOT * HID / 4;
    const dim3 cgrid(n4 / 256);
    const dim3 wgrid(HID / 64, HID / 64);      // (32, 32)
    const dim3 ggrid(HID / BN, MTOT / BM);     // (16, 32)
    const dim3 blk(256);

    // Split X and weights into bf16 hi/lo (weights also transposed to [N,K])
    convert_hilo_kernel<<<cgrid, blk>>>(X, xhi, xlo, n4);
    convert_wt_kernel<<<wgrid, blk>>>(Wq, whi + 0 * WSZ, wlo + 0 * WSZ);
    convert_wt_kernel<<<wgrid, blk>>>(Wk, whi + 1 * WSZ, wlo + 1 * WSZ);
    convert_wt_kernel<<<wgrid, blk>>>(Wv, whi + 2 * WSZ, wlo + 2 * WSZ);
    convert_wt_kernel<<<wgrid, blk>>>(Wo, whi + 3 * WSZ, wlo + 3 * WSZ);

    // Q/K/V projections (tensor cores), head-split epilogue
    gemm_bf16x3_kernel<<<ggrid, blk, GEMM_SMEM_BYTES>>>(xhi, xlo, whi + 0 * WSZ, wlo + 0 * WSZ, bq, q, 1);
    gemm_bf16x3_kernel<<<ggrid, blk, GEMM_SMEM_BYTES>>>(xhi, xlo, whi + 1 * WSZ, wlo + 1 * WSZ, bk, k, 1);
    gemm_bf16x3_kernel<<<ggrid, blk, GEMM_SMEM_BYTES>>>(xhi, xlo, whi + 2 * WSZ, wlo + 2 * WSZ, bv, v, 1);

    // Attention (fp32 flash, unchanged)
    attn_kernel<<<dim3(SEQ / 64, BATCH * NHEADS), blk, ATTN_SMEM_BYTES>>>(q, k, v, attn);

    // Output projection
    convert_hilo_kernel<<<cgrid, blk>>>(attn, ahi, alo, n4);
    gemm_bf16x3_kernel<<<ggrid, blk, GEMM_SMEM_BYTES>>>(ahi, alo, whi + 3 * WSZ, wlo + 3 * WSZ, bo, out, 0);
}

// round 9
// speedup vs baseline: 3.1075x; 2.1823x over previous
#include <cuda_runtime.h>
#include <cuda_bf16.h>
#include <cstdint>

#define HID    2048
#define NHEADS 16
#define HD     128
#define BATCH  2
#define SEQ    2048
#define MTOT   (BATCH * SEQ)   // 4096

// ---------------------------------------------------------------------------
// Scratch (static device arrays; no cudaMalloc anywhere)
// ---------------------------------------------------------------------------
__device__ __nv_bfloat16 g_xhi[(size_t)MTOT * HID];
__device__ __nv_bfloat16 g_xlo[(size_t)MTOT * HID];
__device__ __nv_bfloat16 g_qhi[(size_t)MTOT * HID];
__device__ __nv_bfloat16 g_qlo[(size_t)MTOT * HID];
__device__ __nv_bfloat16 g_khi[(size_t)MTOT * HID];
__device__ __nv_bfloat16 g_klo[(size_t)MTOT * HID];
__device__ __nv_bfloat16 g_vhi[(size_t)MTOT * HID];
__device__ __nv_bfloat16 g_vlo[(size_t)MTOT * HID];
__device__ __nv_bfloat16 g_vthi[(size_t)MTOT * HID];   // [b,h,d,s]
__device__ __nv_bfloat16 g_vtlo[(size_t)MTOT * HID];
__device__ __nv_bfloat16 g_ahi[(size_t)MTOT * HID];
__device__ __nv_bfloat16 g_alo[(size_t)MTOT * HID];
__device__ __nv_bfloat16 g_whi[4][(size_t)HID * HID];  // [N][K] transposed
__device__ __nv_bfloat16 g_wlo[4][(size_t)HID * HID];

// ---------------------------------------------------------------------------
// PTX helpers — base-target-safe only (no tcgen05 at compute_103)
// ---------------------------------------------------------------------------
static __device__ __forceinline__ uint32_t smem_u32(const void* p) {
    return (uint32_t)__cvta_generic_to_shared(p);
}

#define CP_ASYNC16(dst, src) \
    asm volatile("cp.async.cg.shared.global [%0], [%1], 16;" \
        :: "r"(dst), "l"(src) : "memory")
#define CP_COMMIT() asm volatile("cp.async.commit_group;" ::: "memory")
#define CP_WAIT_1() asm volatile("cp.async.wait_group 1;" ::: "memory")
#define CP_WAIT_0() asm volatile("cp.async.wait_group 0;" ::: "memory")

#define LDSM_X4(r0, r1, r2, r3, addr) \
    asm volatile("ldmatrix.sync.aligned.m8n8.x4.shared.b16 {%0,%1,%2,%3}, [%4];" \
        : "=r"(r0), "=r"(r1), "=r"(r2), "=r"(r3) : "r"(addr))

#define MMA_BF16(c, a, b0, b1) \
    asm volatile("mma.sync.aligned.m16n8k16.row.col.f32.bf16.bf16.f32 " \
        "{%0,%1,%2,%3}, {%4,%5,%6,%7}, {%8,%9}, {%0,%1,%2,%3};" \
        : "+f"((c)[0]), "+f"((c)[1]), "+f"((c)[2]), "+f"((c)[3]) \
        : "r"((a)[0]), "r"((a)[1]), "r"((a)[2]), "r"((a)[3]), "r"(b0), "r"(b1))

// fast 2^y on the FMA pipe (avoids MUFU throughput ceiling)
static __device__ __forceinline__ float fast_exp2(float y) {
    y = fmaxf(y, -80.f);
    float fl = floorf(y);
    float f = y - fl;
    float p = 0.0013333558f;
    p = fmaf(p, f, 0.0096181291f);
    p = fmaf(p, f, 0.0555041087f);
    p = fmaf(p, f, 0.2402265070f);
    p = fmaf(p, f, 0.6931471806f);
    p = fmaf(p, f, 1.0f);
    int i = (int)fl;
    return p * __int_as_float((i + 127) << 23);
}

static __device__ __forceinline__ void split_pack(
    float v0, float v1, uint32_t& hi, uint32_t& lo)
{
    __align__(4) __nv_bfloat16 hh[2], ll[2];
    hh[0] = __float2bfloat16(v0);
    hh[1] = __float2bfloat16(v1);
    ll[0] = __float2bfloat16(v0 - __bfloat162float(hh[0]));
    ll[1] = __float2bfloat16(v1 - __bfloat162float(hh[1]));
    hi = *(uint32_t*)hh;
    lo = *(uint32_t*)ll;
}

// ---------------------------------------------------------------------------
// Convert: fp32 -> (bf16 hi, bf16 lo), elementwise (for X)
// ---------------------------------------------------------------------------
__global__ __launch_bounds__(256) void convert_hilo_kernel(
    const float* __restrict__ X, __nv_bfloat16* __restrict__ hi,
    __nv_bfloat16* __restrict__ lo, int n4)
{
    int i = blockIdx.x * blockDim.x + threadIdx.x;
    if (i >= n4) return;
    float4 v = ((const float4*)X)[i];
    float xs[4] = {v.x, v.y, v.z, v.w};
    __align__(8) __nv_bfloat16 h[4], l[4];
#pragma unroll
    for (int j = 0; j < 4; ++j) {
        h[j] = __float2bfloat16(xs[j]);
        l[j] = __float2bfloat16(xs[j] - __bfloat162float(h[j]));
    }
    ((uint2*)hi)[i] = *(const uint2*)h;
    ((uint2*)lo)[i] = *(const uint2*)l;
}

// ---------------------------------------------------------------------------
// Convert + transpose: W fp32 [K,N] -> hi/lo bf16 [N,K]
// ---------------------------------------------------------------------------
__global__ __launch_bounds__(256) void convert_wt_kernel(
    const float* __restrict__ W, __nv_bfloat16* __restrict__ hi,
    __nv_bfloat16* __restrict__ lo)
{
    __shared__ float sm[64][65];
    const int k0 = blockIdx.y * 64, n0 = blockIdx.x * 64;
    const int tid = threadIdx.x;
#pragma unroll
    for (int i = 0; i < 4; ++i) {
        int id = tid + i * 256;
        int r = id >> 4, g = id & 15;
        float4 v = *(const float4*)(W + (size_t)(k0 + r) * HID + n0 + g * 4);
        sm[r][g * 4 + 0] = v.x; sm[r][g * 4 + 1] = v.y;
        sm[r][g * 4 + 2] = v.z; sm[r][g * 4 + 3] = v.w;
    }
    __syncthreads();
#pragma unroll
    for (int i = 0; i < 4; ++i) {
        int id = tid + i * 256;
        int r = id >> 4, g = id & 15;
        __align__(8) __nv_bfloat16 h[4], l[4];
#pragma unroll
        for (int j = 0; j < 4; ++j) {
            float x = sm[g * 4 + j][r];
            h[j] = __float2bfloat16(x);
            l[j] = __float2bfloat16(x - __bfloat162float(h[j]));
        }
        size_t off = (size_t)(n0 + r) * HID + k0 + g * 4;
        *(uint2*)(hi + off) = *(const uint2*)h;
        *(uint2*)(lo + off) = *(const uint2*)l;
    }
}

// ---------------------------------------------------------------------------
// bf16 transpose per head: [b,h,s,d] -> [b,h,d,s]  (hi and lo)
// grid (32 s-tiles, 2 d-tiles, 32 bh), 64x64 tiles
// ---------------------------------------------------------------------------
__global__ __launch_bounds__(256) void vtrans_kernel(
    const __nv_bfloat16* __restrict__ vhi, const __nv_bfloat16* __restrict__ vlo,
    __nv_bfloat16* __restrict__ vthi, __nv_bfloat16* __restrict__ vtlo)
{
    __shared__ __nv_bfloat16 ts[64][72];
    const int s0 = blockIdx.x * 64, d0 = blockIdx.y * 64;
    const int bh = blockIdx.z;
    const int tid = threadIdx.x;
    const size_t base = (size_t)bh * SEQ * HD;
    const size_t tbase = (size_t)bh * HD * SEQ;

#pragma unroll
    for (int m = 0; m < 2; ++m) {
        const __nv_bfloat16* src = m ? vlo : vhi;
        __nv_bfloat16* dst = m ? vtlo : vthi;
#pragma unroll
        for (int i = 0; i < 4; ++i) {
            int idx = tid + i * 256;
            int r = idx >> 4, ch = idx & 15;
            uint2 v = *(const uint2*)(src + base + (size_t)(s0 + r) * HD + d0 + ch * 4);
            *(uint2*)&ts[r][ch * 4] = v;
        }
        __syncthreads();
#pragma unroll
        for (int i = 0; i < 4; ++i) {
            int idx = tid + i * 256;
            int r = idx >> 4, ch = idx & 15;   // r = d-local row, ch*4 = s-local
            __align__(8) __nv_bfloat16 t[4];
#pragma unroll
            for (int j = 0; j < 4; ++j) t[j] = ts[ch * 4 + j][r];
            *(uint2*)(dst + tbase + (size_t)(d0 + r) * SEQ + s0 + ch * 4) = *(const uint2*)t;
        }
        __syncthreads();
    }
}

// ---------------------------------------------------------------------------
// 3xBF16 tensor-core GEMM via mma.sync: C[4096,2048] = A @ B^T + bias
// mode 0: fp32 [M,HID] out; mode 1: bf16 hi/lo out, head-split [b,h,s,d]
// ---------------------------------------------------------------------------
#define BM 128
#define BN 128
#define BK 32
#define KT (HID / BK)          // 64
#define ROWB 80
#define TILE_B (128 * ROWB)
#define STAGE_B (4 * TILE_B)
#define GEMM_SMEM_BYTES (2 * STAGE_B)  // 81920

static __device__ __forceinline__ void load_stage(
    const __nv_bfloat16* __restrict__ Ahi, const __nv_bfloat16* __restrict__ Alo,
    const __nv_bfloat16* __restrict__ Bhi, const __nv_bfloat16* __restrict__ Blo,
    int bm, int bn, int k0, uint32_t s_base, int tid)
{
#pragma unroll
    for (int i = 0; i < 8; ++i) {
        const int mat = i >> 1;
        const int idx = ((i & 1) << 8) + tid;
        const int row = idx >> 2;
        const int ch  = idx & 3;
        const int grow = (mat < 2 ? bm : bn) + row;
        const __nv_bfloat16* src =
            (mat == 0 ? Ahi : mat == 1 ? Alo : mat == 2 ? Bhi : Blo)
            + (size_t)grow * HID + k0 + ch * 8;
        const uint32_t dst = s_base + mat * TILE_B + row * ROWB + ch * 16;
        CP_ASYNC16(dst, src);
    }
}

__global__ __launch_bounds__(256) void gemm_bf16x3_kernel(
    const __nv_bfloat16* __restrict__ Ahi, const __nv_bfloat16* __restrict__ Alo,
    const __nv_bfloat16* __restrict__ Bhi, const __nv_bfloat16* __restrict__ Blo,
    const float* __restrict__ bias, float* __restrict__ Cf,
    __nv_bfloat16* __restrict__ Chi, __nv_bfloat16* __restrict__ Clo, int mode)
{
    extern __shared__ char smc[];
    const uint32_t s_base = smem_u32(smc);
    const int tid  = threadIdx.x;
    const int wid  = tid >> 5, lane = tid & 31;
    const int wm   = wid & 1, wn = wid >> 1;
    const int m_base = wm * 64, n_base = wn * 32;
    const int bm = blockIdx.y * BM, bn = blockIdx.x * BN;

    float c[4][4][4];
#pragma unroll
    for (int i = 0; i < 4; ++i)
#pragma unroll
        for (int j = 0; j < 4; ++j)
#pragma unroll
            for (int r = 0; r < 4; ++r) c[i][j][r] = 0.f;

    const int a_r = lane & 15;
    const int a_c = (lane & 16) ? 8 : 0;
    const int b_r = (lane & 7) + ((lane & 16) ? 8 : 0);
    const int b_c = (lane & 8) ? 8 : 0;

    load_stage(Ahi, Alo, Bhi, Blo, bm, bn, 0, s_base, tid);
    CP_COMMIT();

    for (int t = 0; t < KT; ++t) {
        if (t + 1 < KT) {
            load_stage(Ahi, Alo, Bhi, Blo, bm, bn, (t + 1) * BK,
                       s_base + ((t + 1) & 1) * STAGE_B, tid);
            CP_COMMIT();
            CP_WAIT_1();
        } else {
            CP_WAIT_0();
        }
        __syncthreads();

        const uint32_t sb  = s_base + (t & 1) * STAGE_B;
        const uint32_t sAh = sb;
        const uint32_t sAl = sb + TILE_B;
        const uint32_t sBh = sb + 2 * TILE_B;
        const uint32_t sBl = sb + 3 * TILE_B;

#pragma unroll
        for (int ks = 0; ks < 2; ++ks) {
            const int kofs = ks * 16;
            uint32_t ah[4][4], al[4][4], bh[2][4], bl[2][4];
#pragma unroll
            for (int mf = 0; mf < 4; ++mf) {
                const uint32_t ra = (uint32_t)((m_base + mf * 16 + a_r) * ROWB
                                               + (kofs + a_c) * 2);
                LDSM_X4(ah[mf][0], ah[mf][1], ah[mf][2], ah[mf][3], sAh + ra);
                LDSM_X4(al[mf][0], al[mf][1], al[mf][2], al[mf][3], sAl + ra);
            }
#pragma unroll
            for (int nb = 0; nb < 2; ++nb) {
                const uint32_t rb = (uint32_t)((n_base + nb * 16 + b_r) * ROWB
                                               + (kofs + b_c) * 2);
                LDSM_X4(bh[nb][0], bh[nb][1], bh[nb][2], bh[nb][3], sBh + rb);
                LDSM_X4(bl[nb][0], bl[nb][1], bl[nb][2], bl[nb][3], sBl + rb);
            }
#pragma unroll
            for (int mf = 0; mf < 4; ++mf)
#pragma unroll
                for (int nf = 0; nf < 4; ++nf) {
                    const int nb = nf >> 1, sel = (nf & 1) * 2;
                    MMA_BF16(c[mf][nf], ah[mf], bh[nb][sel], bh[nb][sel + 1]);
                    MMA_BF16(c[mf][nf], ah[mf], bl[nb][sel], bl[nb][sel + 1]);
                    MMA_BF16(c[mf][nf], al[mf], bh[nb][sel], bh[nb][sel + 1]);
                }
        }
        __syncthreads();
    }

    const int g = lane >> 2, t4 = lane & 3;
#pragma unroll
    for (int mf = 0; mf < 4; ++mf) {
#pragma unroll
        for (int nf = 0; nf < 4; ++nf) {
            const int cb = bn + n_base + nf * 8 + t4 * 2;
            const float b0 = bias[cb], b1 = bias[cb + 1];
#pragma unroll
            for (int half = 0; half < 2; ++half) {
                const int row = bm + m_base + mf * 16 + g + half * 8;
                const float v0 = c[mf][nf][half * 2 + 0] + b0;
                const float v1 = c[mf][nf][half * 2 + 1] + b1;
                if (mode == 0) {
                    float2 v; v.x = v0; v.y = v1;
                    *(float2*)(Cf + (size_t)row * HID + cb) = v;
                } else {
                    const int b = row >> 11, s = row & 2047;
                    const int h = cb >> 7, d = cb & 127;
                    const size_t off = (((size_t)(b * NHEADS + h)) * SEQ + s) * HD + d;
                    uint32_t hi, lo;
                    split_pack(v0, v1, hi, lo);
                    *(uint32_t*)(Chi + off) = hi;
                    *(uint32_t*)(Clo + off) = lo;
                }
            }
        }
    }
}

// ---------------------------------------------------------------------------
// Flash attention via mma.sync bf16 hi/lo 3-pass, online softmax (log2 domain)
// CTA: 128 Q rows x one (b,h). KV chunks of 64, cp.async double-buffered.
// ---------------------------------------------------------------------------
#define AT_QROW 272
#define AT_KROW 272
#define AT_VROW 144
#define AT_QHI 0
#define AT_QLO 34816
#define AT_STAGE0 69632
#define AT_STAGEB 71680
#define AT_KHI 0
#define AT_KLO 17408
#define AT_VHI 34816
#define AT_VLO 53248
#define ATTN_SMEM (AT_STAGE0 + 2 * AT_STAGEB)   // 212992

static __device__ __forceinline__ void attn_load_kv(
    const __nv_bfloat16* __restrict__ Khi, const __nv_bfloat16* __restrict__ Klo,
    const __nv_bfloat16* __restrict__ Vthi, const __nv_bfloat16* __restrict__ Vtlo,
    size_t hbase, size_t vbase, int kv0, uint32_t stage, int tid)
{
#pragma unroll
    for (int i = 0; i < 4; ++i) {
        const int idx = tid + i * 256;         // 0..1023
        const int r  = idx >> 4, ch = idx & 15;
        CP_ASYNC16(stage + AT_KHI + r * AT_KROW + ch * 16,
                   Khi + hbase + (size_t)(kv0 + r) * HD + ch * 8);
        CP_ASYNC16(stage + AT_KLO + r * AT_KROW + ch * 16,
                   Klo + hbase + (size_t)(kv0 + r) * HD + ch * 8);
        const int vr = idx >> 3, vch = idx & 7;
        CP_ASYNC16(stage + AT_VHI + vr * AT_VROW + vch * 16,
                   Vthi + vbase + (size_t)vr * SEQ + kv0 + vch * 8);
        CP_ASYNC16(stage + AT_VLO + vr * AT_VROW + vch * 16,
                   Vtlo + vbase + (size_t)vr * SEQ + kv0 + vch * 8);
    }
}

__global__ __launch_bounds__(256) void attn_mma_kernel(
    const __nv_bfloat16* __restrict__ Qhi, const __nv_bfloat16* __restrict__ Qlo,
    const __nv_bfloat16* __restrict__ Khi, const __nv_bfloat16* __restrict__ Klo,
    const __nv_bfloat16* __restrict__ Vthi, const __nv_bfloat16* __restrict__ Vtlo,
    __nv_bfloat16* __restrict__ Ohi, __nv_bfloat16* __restrict__ Olo)
{
    extern __shared__ char smc[];
    const uint32_t sb = smem_u32(smc);
    const int tid = threadIdx.x, wid = tid >> 5, lane = tid & 31;
    const int bh = blockIdx.y, qt = blockIdx.x;
    const int g = lane >> 2, t4 = lane & 3;
    const int wm = wid * 16;
    const float CSCL = 0.12751743f;   // (1/sqrt(128)) * log2(e)

    const size_t hbase = (size_t)bh * SEQ * HD;
    const size_t vbase = (size_t)bh * HD * SEQ;
    const int s0 = qt * 128;

    // Q tile (persistent in smem)
#pragma unroll
    for (int i = 0; i < 8; ++i) {
        const int idx = tid + i * 256;
        const int r = idx >> 4, ch = idx & 15;
        CP_ASYNC16(sb + AT_QHI + r * AT_QROW + ch * 16,
                   Qhi + hbase + (size_t)(s0 + r) * HD + ch * 8);
        CP_ASYNC16(sb + AT_QLO + r * AT_QROW + ch * 16,
                   Qlo + hbase + (size_t)(s0 + r) * HD + ch * 8);
    }
    attn_load_kv(Khi, Klo, Vthi, Vtlo, hbase, vbase, 0, sb + AT_STAGE0, tid);
    CP_COMMIT();
    attn_load_kv(Khi, Klo, Vthi, Vtlo, hbase, vbase, 64, sb + AT_STAGE0 + AT_STAGEB, tid);
    CP_COMMIT();

    float o[16][4];
#pragma unroll
    for (int nf = 0; nf < 16; ++nf)
#pragma unroll
        for (int r = 0; r < 4; ++r) o[nf][r] = 0.f;
    float m0 = -1e30f, m1 = -1e30f, l0 = 0.f, l1 = 0.f;

    const int a_r = lane & 15;
    const int a_c = (lane & 16) ? 8 : 0;
    const int b_r = (lane & 7) + ((lane & 16) ? 8 : 0);
    const int b_c = (lane & 8) ? 8 : 0;

    for (int t = 0; t < SEQ / 64; ++t) {
        if (t < SEQ / 64 - 1) { CP_WAIT_1(); } else { CP_WAIT_0(); }
        __syncthreads();
        const uint32_t st = sb + AT_STAGE0 + (t & 1) * AT_STAGEB;

        // ---- scores = Q K^T (hi/lo 3-pass)
        float sc[8][4];
#pragma unroll
        for (int nf = 0; nf < 8; ++nf)
#pragma unroll
            for (int r = 0; r < 4; ++r) sc[nf][r] = 0.f;

#pragma unroll
        for (int kb = 0; kb < 8; ++kb) {
            uint32_t qh[4], ql[4];
            const uint32_t qa = sb + AT_QHI + (wm + a_r) * AT_QROW + (kb * 16 + a_c) * 2;
            LDSM_X4(qh[0], qh[1], qh[2], qh[3], qa);
            LDSM_X4(ql[0], ql[1], ql[2], ql[3], qa + (AT_QLO - AT_QHI));
#pragma unroll
            for (int nb = 0; nb < 4; ++nb) {
                uint32_t kh[4], kl[4];
                const uint32_t ka = st + AT_KHI + (nb * 16 + b_r) * AT_KROW
                                    + (kb * 16 + b_c) * 2;
                LDSM_X4(kh[0], kh[1], kh[2], kh[3], ka);
                LDSM_X4(kl[0], kl[1], kl[2], kl[3], ka + (AT_KLO - AT_KHI));
                MMA_BF16(sc[2 * nb],     qh, kh[0], kh[1]);
                MMA_BF16(sc[2 * nb],     qh, kl[0], kl[1]);
                MMA_BF16(sc[2 * nb],     ql, kh[0], kh[1]);
                MMA_BF16(sc[2 * nb + 1], qh, kh[2], kh[3]);
                MMA_BF16(sc[2 * nb + 1], qh, kl[2], kl[3]);
                MMA_BF16(sc[2 * nb + 1], ql, kh[2], kh[3]);
            }
        }

        // ---- online softmax (base-2)
        float mx0 = -1e30f, mx1 = -1e30f;
#pragma unroll
        for (int nf = 0; nf < 8; ++nf) {
            sc[nf][0] *= CSCL; sc[nf][1] *= CSCL;
            sc[nf][2] *= CSCL; sc[nf][3] *= CSCL;
            mx0 = fmaxf(mx0, fmaxf(sc[nf][0], sc[nf][1]));
            mx1 = fmaxf(mx1, fmaxf(sc[nf][2], sc[nf][3]));
        }
        mx0 = fmaxf(mx0, __shfl_xor_sync(0xffffffffu, mx0, 1));
        mx0 = fmaxf(mx0, __shfl_xor_sync(0xffffffffu, mx0, 2));
        mx1 = fmaxf(mx1, __shfl_xor_sync(0xffffffffu, mx1, 1));
        mx1 = fmaxf(mx1, __shfl_xor_sync(0xffffffffu, mx1, 2));
        const float mn0 = fmaxf(m0, mx0), mn1 = fmaxf(m1, mx1);
        const float cr0 = fast_exp2(m0 - mn0), cr1 = fast_exp2(m1 - mn1);
        m0 = mn0; m1 = mn1;
        float rs0 = 0.f, rs1 = 0.f;
#pragma unroll
        for (int nf = 0; nf < 8; ++nf) {
            sc[nf][0] = fast_exp2(sc[nf][0] - mn0);
            sc[nf][1] = fast_exp2(sc[nf][1] - mn0);
            sc[nf][2] = fast_exp2(sc[nf][2] - mn1);
            sc[nf][3] = fast_exp2(sc[nf][3] - mn1);
            rs0 += sc[nf][0] + sc[nf][1];
            rs1 += sc[nf][2] + sc[nf][3];
        }
        rs0 += __shfl_xor_sync(0xffffffffu, rs0, 1);
        rs0 += __shfl_xor_sync(0xffffffffu, rs0, 2);
        rs1 += __shfl_xor_sync(0xffffffffu, rs1, 1);
        rs1 += __shfl_xor_sync(0xffffffffu, rs1, 2);
        l0 = l0 * cr0 + rs0;
        l1 = l1 * cr1 + rs1;
#pragma unroll
        for (int nf = 0; nf < 16; ++nf) {
            o[nf][0] *= cr0; o[nf][1] *= cr0;
            o[nf][2] *= cr1; o[nf][3] *= cr1;
        }

        // ---- O += P V (P hi/lo from score frags; V^T non-trans B path)
#pragma unroll
        for (int kb = 0; kb < 4; ++kb) {
            uint32_t pah[4], pal[4];
#pragma unroll
            for (int jj = 0; jj < 2; ++jj) {
                const int j = 2 * kb + jj;
                split_pack(sc[j][0], sc[j][1], pah[2 * jj], pal[2 * jj]);
                split_pack(sc[j][2], sc[j][3], pah[2 * jj + 1], pal[2 * jj + 1]);
            }
#pragma unroll
            for (int nb = 0; nb < 8; ++nb) {
                uint32_t vh[4], vl[4];
                const uint32_t va = st + AT_VHI + (nb * 16 + b_r) * AT_VROW
                                    + (kb * 16 + b_c) * 2;
                LDSM_X4(vh[0], vh[1], vh[2], vh[3], va);
                LDSM_X4(vl[0], vl[1], vl[2], vl[3], va + (AT_VLO - AT_VHI));
                MMA_BF16(o[2 * nb],     pah, vh[0], vh[1]);
                MMA_BF16(o[2 * nb],     pah, vl[0], vl[1]);
                MMA_BF16(o[2 * nb],     pal, vh[0], vh[1]);
                MMA_BF16(o[2 * nb + 1], pah, vh[2], vh[3]);
                MMA_BF16(o[2 * nb + 1], pah, vl[2], vl[3]);
                MMA_BF16(o[2 * nb + 1], pal, vh[2], vh[3]);
            }
        }
        __syncthreads();
        if (t + 2 < SEQ / 64) {
            attn_load_kv(Khi, Klo, Vthi, Vtlo, hbase, vbase, (t + 2) * 64,
                         sb + AT_STAGE0 + (t & 1) * AT_STAGEB, tid);
            CP_COMMIT();
        }
    }

    // ---- epilogue: normalize, split hi/lo, write merged [B*S, HID]
    const float inv0 = 1.f / l0, inv1 = 1.f / l1;
    const int b = bh >> 4, h = bh & 15;
    const size_t r0 = (size_t)b * SEQ + s0 + wm + g;
    const size_t r1 = r0 + 8;
#pragma unroll
    for (int nf = 0; nf < 16; ++nf) {
        const int col = h * HD + nf * 8 + t4 * 2;
        uint32_t hi, lo;
        split_pack(o[nf][0] * inv0, o[nf][1] * inv0, hi, lo);
        *(uint32_t*)(Ohi + r0 * HID + col) = hi;
        *(uint32_t*)(Olo + r0 * HID + col) = lo;
        split_pack(o[nf][2] * inv1, o[nf][3] * inv1, hi, lo);
        *(uint32_t*)(Ohi + r1 * HID + col) = hi;
        *(uint32_t*)(Olo + r1 * HID + col) = lo;
    }
}

// ---------------------------------------------------------------------------
extern "C" void kernel_launch(void* const* d_in, const int* in_sizes, int n_in,
                              void* d_out, int out_size) {
    const float* X  = (const float*)d_in[0];
    const float* Wq = (const float*)d_in[1];
    const float* bq = (const float*)d_in[2];
    const float* Wk = (const float*)d_in[3];
    const float* bk = (const float*)d_in[4];
    const float* Wv = (const float*)d_in[5];
    const float* bv = (const float*)d_in[6];
    const float* Wo = (const float*)d_in[7];
    const float* bo = (const float*)d_in[8];
    float* out = (float*)d_out;

    __nv_bfloat16 *xhi, *xlo, *qhi, *qlo, *khi, *klo, *vhi, *vlo;
    __nv_bfloat16 *vthi, *vtlo, *ahi, *alo, *whi, *wlo;
    cudaGetSymbolAddress((void**)&xhi, g_xhi);
    cudaGetSymbolAddress((void**)&xlo, g_xlo);
    cudaGetSymbolAddress((void**)&qhi, g_qhi);
    cudaGetSymbolAddress((void**)&qlo, g_qlo);
    cudaGetSymbolAddress((void**)&khi, g_khi);
    cudaGetSymbolAddress((void**)&klo, g_klo);
    cudaGetSymbolAddress((void**)&vhi, g_vhi);
    cudaGetSymbolAddress((void**)&vlo, g_vlo);
    cudaGetSymbolAddress((void**)&vthi, g_vthi);
    cudaGetSymbolAddress((void**)&vtlo, g_vtlo);
    cudaGetSymbolAddress((void**)&ahi, g_ahi);
    cudaGetSymbolAddress((void**)&alo, g_alo);
    cudaGetSymbolAddress((void**)&whi, g_whi);
    cudaGetSymbolAddress((void**)&wlo, g_wlo);

    cudaFuncSetAttribute(gemm_bf16x3_kernel,
                         cudaFuncAttributeMaxDynamicSharedMemorySize, GEMM_SMEM_BYTES);
    cudaFuncSetAttribute(attn_mma_kernel,
                         cudaFuncAttributeMaxDynamicSharedMemorySize, ATTN_SMEM);

    const size_t WSZ = (size_t)HID * HID;
    const int n4 = MTOT * HID / 4;
    const dim3 cgrid(n4 / 256);
    const dim3 wgrid(HID / 64, HID / 64);
    const dim3 ggrid(HID / BN, MTOT / BM);
    const dim3 blk(256);

    convert_hilo_kernel<<<cgrid, blk>>>(X, xhi, xlo, n4);
    convert_wt_kernel<<<wgrid, blk>>>(Wq, whi + 0 * WSZ, wlo + 0 * WSZ);
    convert_wt_kernel<<<wgrid, blk>>>(Wk, whi + 1 * WSZ, wlo + 1 * WSZ);
    convert_wt_kernel<<<wgrid, blk>>>(Wv, whi + 2 * WSZ, wlo + 2 * WSZ);
    convert_wt_kernel<<<wgrid, blk>>>(Wo, whi + 3 * WSZ, wlo + 3 * WSZ);

    gemm_bf16x3_kernel<<<ggrid, blk, GEMM_SMEM_BYTES>>>(
        xhi, xlo, whi + 0 * WSZ, wlo + 0 * WSZ, bq, nullptr, qhi, qlo, 1);
    gemm_bf16x3_kernel<<<ggrid, blk, GEMM_SMEM_BYTES>>>(
        xhi, xlo, whi + 1 * WSZ, wlo + 1 * WSZ, bk, nullptr, khi, klo, 1);
    gemm_bf16x3_kernel<<<ggrid, blk, GEMM_SMEM_BYTES>>>(
        xhi, xlo, whi + 2 * WSZ, wlo + 2 * WSZ, bv, nullptr, vhi, vlo, 1);

    vtrans_kernel<<<dim3(SEQ / 64, HD / 64, BATCH * NHEADS), blk>>>(vhi, vlo, vthi, vtlo);

    attn_mma_kernel<<<dim3(SEQ / 128, BATCH * NHEADS), blk, ATTN_SMEM>>>(
        qhi, qlo, khi, klo, vthi, vtlo, ahi, alo);

    gemm_bf16x3_kernel<<<ggrid, blk, GEMM_SMEM_BYTES>>>(
        ahi, alo, whi + 3 * WSZ, wlo + 3 * WSZ, bo, out, nullptr, nullptr, 0);
}

// round 10
// speedup vs baseline: 4.8791x; 1.5701x over previous
#include <cuda_runtime.h>
#include <cuda_fp16.h>
#include <cstdint>

#define HID    2048
#define NHEADS 16
#define HD     128
#define BATCH  2
#define SEQ    2048
#define MTOT   (BATCH * SEQ)   // 4096

// ---------------------------------------------------------------------------
// Scratch (static device arrays; no cudaMalloc anywhere)
// ---------------------------------------------------------------------------
__device__ __half g_xhi[(size_t)MTOT * HID];
__device__ __half g_xlo[(size_t)MTOT * HID];
__device__ __half g_qhi[(size_t)MTOT * HID];
__device__ __half g_qlo[(size_t)MTOT * HID];
__device__ __half g_k16[(size_t)MTOT * HID];
__device__ __half g_v16[(size_t)MTOT * HID];
__device__ __half g_vt16[(size_t)MTOT * HID];   // [b,h,d,s]
__device__ __half g_ahi[(size_t)MTOT * HID];
__device__ __half g_alo[(size_t)MTOT * HID];
__device__ __half g_w16[4][(size_t)HID * HID];  // [N][K] transposed fp16

// ---------------------------------------------------------------------------
// PTX helpers — base-target-safe only (no tcgen05 at compute_103)
// ---------------------------------------------------------------------------
static __device__ __forceinline__ uint32_t smem_u32(const void* p) {
    return (uint32_t)__cvta_generic_to_shared(p);
}

#define CP_ASYNC16(dst, src) \
    asm volatile("cp.async.cg.shared.global [%0], [%1], 16;" \
        :: "r"(dst), "l"(src) : "memory")
#define CP_COMMIT() asm volatile("cp.async.commit_group;" ::: "memory")
#define CP_WAIT_1() asm volatile("cp.async.wait_group 1;" ::: "memory")
#define CP_WAIT_0() asm volatile("cp.async.wait_group 0;" ::: "memory")

#define LDSM_X4(r0, r1, r2, r3, addr) \
    asm volatile("ldmatrix.sync.aligned.m8n8.x4.shared.b16 {%0,%1,%2,%3}, [%4];" \
        : "=r"(r0), "=r"(r1), "=r"(r2), "=r"(r3) : "r"(addr))

// mma m16n8k16 row.col fp16 -> f32
#define MMA_F16(c, a, b0, b1) \
    asm volatile("mma.sync.aligned.m16n8k16.row.col.f32.f16.f16.f32 " \
        "{%0,%1,%2,%3}, {%4,%5,%6,%7}, {%8,%9}, {%0,%1,%2,%3};" \
        : "+f"((c)[0]), "+f"((c)[1]), "+f"((c)[2]), "+f"((c)[3]) \
        : "r"((a)[0]), "r"((a)[1]), "r"((a)[2]), "r"((a)[3]), "r"(b0), "r"(b1))

// fast 2^y on the FMA pipe (avoids MUFU throughput ceiling)
static __device__ __forceinline__ float fast_exp2(float y) {
    y = fmaxf(y, -80.f);
    float fl = floorf(y);
    float f = y - fl;
    float p = 0.0013333558f;
    p = fmaf(p, f, 0.0096181291f);
    p = fmaf(p, f, 0.0555041087f);
    p = fmaf(p, f, 0.2402265070f);
    p = fmaf(p, f, 0.6931471806f);
    p = fmaf(p, f, 1.0f);
    int i = (int)fl;
    return p * __int_as_float((i + 127) << 23);
}

// split two fp32 into packed fp16 (hi) + packed fp16 residual (lo)
static __device__ __forceinline__ void split_pack_h(
    float v0, float v1, uint32_t& hi, uint32_t& lo)
{
    const __half h0 = __float2half_rn(v0), h1 = __float2half_rn(v1);
    const __half l0 = __float2half_rn(v0 - __half2float(h0));
    const __half l1 = __float2half_rn(v1 - __half2float(h1));
    __align__(4) __half hh[2] = {h0, h1};
    __align__(4) __half ll[2] = {l0, l1};
    hi = *(const uint32_t*)hh;
    lo = *(const uint32_t*)ll;
}

// ---------------------------------------------------------------------------
// Convert: fp32 -> (fp16 hi, fp16 lo), elementwise (for X)
// ---------------------------------------------------------------------------
__global__ __launch_bounds__(256) void convert_hilo_kernel(
    const float* __restrict__ X, __half* __restrict__ hi,
    __half* __restrict__ lo, int n4)
{
    int i = blockIdx.x * blockDim.x + threadIdx.x;
    if (i >= n4) return;
    float4 v = ((const float4*)X)[i];
    float xs[4] = {v.x, v.y, v.z, v.w};
    __align__(8) __half h[4], l[4];
#pragma unroll
    for (int j = 0; j < 4; ++j) {
        h[j] = __float2half_rn(xs[j]);
        l[j] = __float2half_rn(xs[j] - __half2float(h[j]));
    }
    ((uint2*)hi)[i] = *(const uint2*)h;
    ((uint2*)lo)[i] = *(const uint2*)l;
}

// ---------------------------------------------------------------------------
// Convert + transpose: W fp32 [K,N] -> single fp16 [N,K]
// ---------------------------------------------------------------------------
__global__ __launch_bounds__(256) void convert_wt_kernel(
    const float* __restrict__ W, __half* __restrict__ w16)
{
    __shared__ float sm[64][65];
    const int k0 = blockIdx.y * 64, n0 = blockIdx.x * 64;
    const int tid = threadIdx.x;
#pragma unroll
    for (int i = 0; i < 4; ++i) {
        int id = tid + i * 256;
        int r = id >> 4, g = id & 15;
        float4 v = *(const float4*)(W + (size_t)(k0 + r) * HID + n0 + g * 4);
        sm[r][g * 4 + 0] = v.x; sm[r][g * 4 + 1] = v.y;
        sm[r][g * 4 + 2] = v.z; sm[r][g * 4 + 3] = v.w;
    }
    __syncthreads();
#pragma unroll
    for (int i = 0; i < 4; ++i) {
        int id = tid + i * 256;
        int r = id >> 4, g = id & 15;
        __align__(8) __half h[4];
#pragma unroll
        for (int j = 0; j < 4; ++j)
            h[j] = __float2half_rn(sm[g * 4 + j][r]);
        *(uint2*)(w16 + (size_t)(n0 + r) * HID + k0 + g * 4) = *(const uint2*)h;
    }
}

// ---------------------------------------------------------------------------
// fp16 transpose per head: [b,h,s,d] -> [b,h,d,s]
// ---------------------------------------------------------------------------
__global__ __launch_bounds__(256) void vtrans_kernel(
    const __half* __restrict__ v16, __half* __restrict__ vt16)
{
    __shared__ __half ts[64][72];
    const int s0 = blockIdx.x * 64, d0 = blockIdx.y * 64;
    const int bh = blockIdx.z;
    const int tid = threadIdx.x;
    const size_t base = (size_t)bh * SEQ * HD;
    const size_t tbase = (size_t)bh * HD * SEQ;

#pragma unroll
    for (int i = 0; i < 4; ++i) {
        int idx = tid + i * 256;
        int r = idx >> 4, ch = idx & 15;
        uint2 v = *(const uint2*)(v16 + base + (size_t)(s0 + r) * HD + d0 + ch * 4);
        *(uint2*)&ts[r][ch * 4] = v;
    }
    __syncthreads();
#pragma unroll
    for (int i = 0; i < 4; ++i) {
        int idx = tid + i * 256;
        int r = idx >> 4, ch = idx & 15;
        __align__(8) __half t[4];
#pragma unroll
        for (int j = 0; j < 4; ++j) t[j] = ts[ch * 4 + j][r];
        *(uint2*)(vt16 + tbase + (size_t)(d0 + r) * SEQ + s0 + ch * 4) = *(const uint2*)t;
    }
}

// ---------------------------------------------------------------------------
// 2-pass fp16 tensor-core GEMM: C[4096,2048] = (Ahi+Alo) @ B^T + bias
//   A split exact fp16 hi/lo [M,K]; B single fp16 [N,K] (pre-transposed).
// mode 0: fp32 [M,HID] out
// mode 1: fp16 hi/lo out, head-split [b,h,s,d]   (Q)
// mode 2: fp16 single out, head-split [b,h,s,d]  (K, V)
// ---------------------------------------------------------------------------
#define BM 128
#define BN 128
#define BK 32
#define KT (HID / BK)          // 64
#define ROWB 80
#define TILE_B (128 * ROWB)    // 10240
#define STAGE_B (3 * TILE_B)   // 30720: Ahi, Alo, B
#define GEMM_SMEM_BYTES (2 * STAGE_B)  // 61440

static __device__ __forceinline__ void load_stage(
    const __half* __restrict__ Ahi, const __half* __restrict__ Alo,
    const __half* __restrict__ B16,
    int bm, int bn, int k0, uint32_t s_base, int tid)
{
#pragma unroll
    for (int i = 0; i < 6; ++i) {
        const int mat = i >> 1;                 // 0:Ahi 1:Alo 2:B
        const int idx = ((i & 1) << 8) + tid;   // 0..511
        const int row = idx >> 2;
        const int ch  = idx & 3;
        const int grow = (mat < 2 ? bm : bn) + row;
        const __half* src =
            (mat == 0 ? Ahi : mat == 1 ? Alo : B16)
            + (size_t)grow * HID + k0 + ch * 8;
        const uint32_t dst = s_base + mat * TILE_B + row * ROWB + ch * 16;
        CP_ASYNC16(dst, src);
    }
}

__global__ __launch_bounds__(256) void gemm_f16x2_kernel(
    const __half* __restrict__ Ahi, const __half* __restrict__ Alo,
    const __half* __restrict__ B16,
    const float* __restrict__ bias, float* __restrict__ Cf,
    __half* __restrict__ Chi, __half* __restrict__ Clo, int mode)
{
    extern __shared__ char smc[];
    const uint32_t s_base = smem_u32(smc);
    const int tid  = threadIdx.x;
    const int wid  = tid >> 5, lane = tid & 31;
    const int wm   = wid & 1, wn = wid >> 1;
    const int m_base = wm * 64, n_base = wn * 32;
    const int bm = blockIdx.y * BM, bn = blockIdx.x * BN;

    float c[4][4][4];
#pragma unroll
    for (int i = 0; i < 4; ++i)
#pragma unroll
        for (int j = 0; j < 4; ++j)
#pragma unroll
            for (int r = 0; r < 4; ++r) c[i][j][r] = 0.f;

    const int a_r = lane & 15;
    const int a_c = (lane & 16) ? 8 : 0;
    const int b_r = (lane & 7) + ((lane & 16) ? 8 : 0);
    const int b_c = (lane & 8) ? 8 : 0;

    load_stage(Ahi, Alo, B16, bm, bn, 0, s_base, tid);
    CP_COMMIT();

    for (int t = 0; t < KT; ++t) {
        if (t + 1 < KT) {
            load_stage(Ahi, Alo, B16, bm, bn, (t + 1) * BK,
                       s_base + ((t + 1) & 1) * STAGE_B, tid);
            CP_COMMIT();
            CP_WAIT_1();
        } else {
            CP_WAIT_0();
        }
        __syncthreads();

        const uint32_t sb  = s_base + (t & 1) * STAGE_B;
        const uint32_t sAh = sb;
        const uint32_t sAl = sb + TILE_B;
        const uint32_t sB  = sb + 2 * TILE_B;

#pragma unroll
        for (int ks = 0; ks < 2; ++ks) {
            const int kofs = ks * 16;
            uint32_t ah[4][4], al[4][4], bh[2][4];
#pragma unroll
            for (int mf = 0; mf < 4; ++mf) {
                const uint32_t ra = (uint32_t)((m_base + mf * 16 + a_r) * ROWB
                                               + (kofs + a_c) * 2);
                LDSM_X4(ah[mf][0], ah[mf][1], ah[mf][2], ah[mf][3], sAh + ra);
                LDSM_X4(al[mf][0], al[mf][1], al[mf][2], al[mf][3], sAl + ra);
            }
#pragma unroll
            for (int nb = 0; nb < 2; ++nb) {
                const uint32_t rb = (uint32_t)((n_base + nb * 16 + b_r) * ROWB
                                               + (kofs + b_c) * 2);
                LDSM_X4(bh[nb][0], bh[nb][1], bh[nb][2], bh[nb][3], sB + rb);
            }
#pragma unroll
            for (int mf = 0; mf < 4; ++mf)
#pragma unroll
                for (int nf = 0; nf < 4; ++nf) {
                    const int nb = nf >> 1, sel = (nf & 1) * 2;
                    MMA_F16(c[mf][nf], ah[mf], bh[nb][sel], bh[nb][sel + 1]);
                    MMA_F16(c[mf][nf], al[mf], bh[nb][sel], bh[nb][sel + 1]);
                }
        }
        __syncthreads();
    }

    const int g = lane >> 2, t4 = lane & 3;
#pragma unroll
    for (int mf = 0; mf < 4; ++mf) {
#pragma unroll
        for (int nf = 0; nf < 4; ++nf) {
            const int cb = bn + n_base + nf * 8 + t4 * 2;
            const float b0 = bias[cb], b1 = bias[cb + 1];
#pragma unroll
            for (int half = 0; half < 2; ++half) {
                const int row = bm + m_base + mf * 16 + g + half * 8;
                const float v0 = c[mf][nf][half * 2 + 0] + b0;
                const float v1 = c[mf][nf][half * 2 + 1] + b1;
                if (mode == 0) {
                    float2 v; v.x = v0; v.y = v1;
                    *(float2*)(Cf + (size_t)row * HID + cb) = v;
                } else {
                    const int b = row >> 11, s = row & 2047;
                    const int h = cb >> 7, d = cb & 127;
                    const size_t off = (((size_t)(b * NHEADS + h)) * SEQ + s) * HD + d;
                    uint32_t hi, lo;
                    split_pack_h(v0, v1, hi, lo);
                    *(uint32_t*)(Chi + off) = hi;
                    if (mode == 1) *(uint32_t*)(Clo + off) = lo;
                }
            }
        }
    }
}

// ---------------------------------------------------------------------------
// Flash attention, fp16 2-pass mma.sync, online softmax (log2 domain)
// CTA: 128 Q rows x one (b,h). KV chunks of 64, cp.async double-buffered.
//   scores = (Qhi + Qlo) . K16;  O = (Phi + Plo) . V16
// ---------------------------------------------------------------------------
#define AT_QROW 272
#define AT_KROW 272
#define AT_VROW 144
#define AT_QHI 0
#define AT_QLO 34816
#define AT_STAGE0 69632
#define AT_K 0
#define AT_V 17408
#define AT_STAGEB 35840
#define ATTN_SMEM (AT_STAGE0 + 2 * AT_STAGEB)   // 141312

static __device__ __forceinline__ void attn_load_kv(
    const __half* __restrict__ K16, const __half* __restrict__ Vt16,
    size_t hbase, size_t vbase, int kv0, uint32_t stage, int tid)
{
#pragma unroll
    for (int i = 0; i < 4; ++i) {
        const int idx = tid + i * 256;         // 0..1023
        const int r  = idx >> 4, ch = idx & 15;
        CP_ASYNC16(stage + AT_K + r * AT_KROW + ch * 16,
                   K16 + hbase + (size_t)(kv0 + r) * HD + ch * 8);
        const int vr = idx >> 3, vch = idx & 7;
        CP_ASYNC16(stage + AT_V + vr * AT_VROW + vch * 16,
                   Vt16 + vbase + (size_t)vr * SEQ + kv0 + vch * 8);
    }
}

__global__ __launch_bounds__(256) void attn_mma_kernel(
    const __half* __restrict__ Qhi, const __half* __restrict__ Qlo,
    const __half* __restrict__ K16, const __half* __restrict__ Vt16,
    __half* __restrict__ Ohi, __half* __restrict__ Olo)
{
    extern __shared__ char smc[];
    const uint32_t sb = smem_u32(smc);
    const int tid = threadIdx.x, wid = tid >> 5, lane = tid & 31;
    const int bh = blockIdx.y, qt = blockIdx.x;
    const int g = lane >> 2, t4 = lane & 3;
    const int wm = wid * 16;
    const float CSCL = 0.12751743f;   // (1/sqrt(128)) * log2(e)

    const size_t hbase = (size_t)bh * SEQ * HD;
    const size_t vbase = (size_t)bh * HD * SEQ;
    const int s0 = qt * 128;

    // Q tile hi/lo (persistent in smem)
#pragma unroll
    for (int i = 0; i < 8; ++i) {
        const int idx = tid + i * 256;
        const int r = idx >> 4, ch = idx & 15;
        CP_ASYNC16(sb + AT_QHI + r * AT_QROW + ch * 16,
                   Qhi + hbase + (size_t)(s0 + r) * HD + ch * 8);
        CP_ASYNC16(sb + AT_QLO + r * AT_QROW + ch * 16,
                   Qlo + hbase + (size_t)(s0 + r) * HD + ch * 8);
    }
    attn_load_kv(K16, Vt16, hbase, vbase, 0, sb + AT_STAGE0, tid);
    CP_COMMIT();
    attn_load_kv(K16, Vt16, hbase, vbase, 64, sb + AT_STAGE0 + AT_STAGEB, tid);
    CP_COMMIT();

    float o[16][4];
#pragma unroll
    for (int nf = 0; nf < 16; ++nf)
#pragma unroll
        for (int r = 0; r < 4; ++r) o[nf][r] = 0.f;
    float m0 = -1e30f, m1 = -1e30f, l0 = 0.f, l1 = 0.f;

    const int a_r = lane & 15;
    const int a_c = (lane & 16) ? 8 : 0;
    const int b_r = (lane & 7) + ((lane & 16) ? 8 : 0);
    const int b_c = (lane & 8) ? 8 : 0;

    for (int t = 0; t < SEQ / 64; ++t) {
        if (t < SEQ / 64 - 1) { CP_WAIT_1(); } else { CP_WAIT_0(); }
        __syncthreads();
        const uint32_t st = sb + AT_STAGE0 + (t & 1) * AT_STAGEB;

        // ---- scores = Q K^T (2-pass: Qhi + Qlo)
        float sc[8][4];
#pragma unroll
        for (int nf = 0; nf < 8; ++nf)
#pragma unroll
            for (int r = 0; r < 4; ++r) sc[nf][r] = 0.f;

#pragma unroll
        for (int kb = 0; kb < 8; ++kb) {
            uint32_t qh[4], ql[4];
            const uint32_t qa = sb + AT_QHI + (wm + a_r) * AT_QROW + (kb * 16 + a_c) * 2;
            LDSM_X4(qh[0], qh[1], qh[2], qh[3], qa);
            LDSM_X4(ql[0], ql[1], ql[2], ql[3], qa + (AT_QLO - AT_QHI));
#pragma unroll
            for (int nb = 0; nb < 4; ++nb) {
                uint32_t kh[4];
                const uint32_t ka = st + AT_K + (nb * 16 + b_r) * AT_KROW
                                    + (kb * 16 + b_c) * 2;
                LDSM_X4(kh[0], kh[1], kh[2], kh[3], ka);
                MMA_F16(sc[2 * nb],     qh, kh[0], kh[1]);
                MMA_F16(sc[2 * nb],     ql, kh[0], kh[1]);
                MMA_F16(sc[2 * nb + 1], qh, kh[2], kh[3]);
                MMA_F16(sc[2 * nb + 1], ql, kh[2], kh[3]);
            }
        }

        // ---- online softmax (base-2)
        float mx0 = -1e30f, mx1 = -1e30f;
#pragma unroll
        for (int nf = 0; nf < 8; ++nf) {
            sc[nf][0] *= CSCL; sc[nf][1] *= CSCL;
            sc[nf][2] *= CSCL; sc[nf][3] *= CSCL;
            mx0 = fmaxf(mx0, fmaxf(sc[nf][0], sc[nf][1]));
            mx1 = fmaxf(mx1, fmaxf(sc[nf][2], sc[nf][3]));
        }
        mx0 = fmaxf(mx0, __shfl_xor_sync(0xffffffffu, mx0, 1));
        mx0 = fmaxf(mx0, __shfl_xor_sync(0xffffffffu, mx0, 2));
        mx1 = fmaxf(mx1, __shfl_xor_sync(0xffffffffu, mx1, 1));
        mx1 = fmaxf(mx1, __shfl_xor_sync(0xffffffffu, mx1, 2));
        const float mn0 = fmaxf(m0, mx0), mn1 = fmaxf(m1, mx1);
        const float cr0 = fast_exp2(m0 - mn0), cr1 = fast_exp2(m1 - mn1);
        m0 = mn0; m1 = mn1;
        float rs0 = 0.f, rs1 = 0.f;
#pragma unroll
        for (int nf = 0; nf < 8; ++nf) {
            sc[nf][0] = fast_exp2(sc[nf][0] - mn0);
            sc[nf][1] = fast_exp2(sc[nf][1] - mn0);
            sc[nf][2] = fast_exp2(sc[nf][2] - mn1);
            sc[nf][3] = fast_exp2(sc[nf][3] - mn1);
            rs0 += sc[nf][0] + sc[nf][1];
            rs1 += sc[nf][2] + sc[nf][3];
        }
        rs0 += __shfl_xor_sync(0xffffffffu, rs0, 1);
        rs0 += __shfl_xor_sync(0xffffffffu, rs0, 2);
        rs1 += __shfl_xor_sync(0xffffffffu, rs1, 1);
        rs1 += __shfl_xor_sync(0xffffffffu, rs1, 2);
        l0 = l0 * cr0 + rs0;
        l1 = l1 * cr1 + rs1;
#pragma unroll
        for (int nf = 0; nf < 16; ++nf) {
            o[nf][0] *= cr0; o[nf][1] *= cr0;
            o[nf][2] *= cr1; o[nf][3] *= cr1;
        }

        // ---- O += P V (P split fp16 hi/lo; V^T single fp16)
#pragma unroll
        for (int kb = 0; kb < 4; ++kb) {
            uint32_t pah[4], pal[4];
#pragma unroll
            for (int jj = 0; jj < 2; ++jj) {
                const int j = 2 * kb + jj;
                split_pack_h(sc[j][0], sc[j][1], pah[2 * jj], pal[2 * jj]);
                split_pack_h(sc[j][2], sc[j][3], pah[2 * jj + 1], pal[2 * jj + 1]);
            }
#pragma unroll
            for (int nb = 0; nb < 8; ++nb) {
                uint32_t vh[4];
                const uint32_t va = st + AT_V + (nb * 16 + b_r) * AT_VROW
                                    + (kb * 16 + b_c) * 2;
                LDSM_X4(vh[0], vh[1], vh[2], vh[3], va);
                MMA_F16(o[2 * nb],     pah, vh[0], vh[1]);
                MMA_F16(o[2 * nb],     pal, vh[0], vh[1]);
                MMA_F16(o[2 * nb + 1], pah, vh[2], vh[3]);
                MMA_F16(o[2 * nb + 1], pal, vh[2], vh[3]);
            }
        }
        __syncthreads();
        if (t + 2 < SEQ / 64) {
            attn_load_kv(K16, Vt16, hbase, vbase, (t + 2) * 64,
                         sb + AT_STAGE0 + (t & 1) * AT_STAGEB, tid);
            CP_COMMIT();
        }
    }

    // ---- epilogue: normalize, split fp16 hi/lo, write merged [B*S, HID]
    const float inv0 = 1.f / l0, inv1 = 1.f / l1;
    const int b = bh >> 4, h = bh & 15;
    const size_t r0 = (size_t)b * SEQ + s0 + wm + g;
    const size_t r1 = r0 + 8;
#pragma unroll
    for (int nf = 0; nf < 16; ++nf) {
        const int col = h * HD + nf * 8 + t4 * 2;
        uint32_t hi, lo;
        split_pack_h(o[nf][0] * inv0, o[nf][1] * inv0, hi, lo);
        *(uint32_t*)(Ohi + r0 * HID + col) = hi;
        *(uint32_t*)(Olo + r0 * HID + col) = lo;
        split_pack_h(o[nf][2] * inv1, o[nf][3] * inv1, hi, lo);
        *(uint32_t*)(Ohi + r1 * HID + col) = hi;
        *(uint32_t*)(Olo + r1 * HID + col) = lo;
    }
}

// ---------------------------------------------------------------------------
extern "C" void kernel_launch(void* const* d_in, const int* in_sizes, int n_in,
                              void* d_out, int out_size) {
    const float* X  = (const float*)d_in[0];
    const float* Wq = (const float*)d_in[1];
    const float* bq = (const float*)d_in[2];
    const float* Wk = (const float*)d_in[3];
    const float* bk = (const float*)d_in[4];
    const float* Wv = (const float*)d_in[5];
    const float* bv = (const float*)d_in[6];
    const float* Wo = (const float*)d_in[7];
    const float* bo = (const float*)d_in[8];
    float* out = (float*)d_out;

    __half *xhi, *xlo, *qhi, *qlo, *k16, *v16, *vt16, *ahi, *alo, *w16;
    cudaGetSymbolAddress((void**)&xhi, g_xhi);
    cudaGetSymbolAddress((void**)&xlo, g_xlo);
    cudaGetSymbolAddress((void**)&qhi, g_qhi);
    cudaGetSymbolAddress((void**)&qlo, g_qlo);
    cudaGetSymbolAddress((void**)&k16, g_k16);
    cudaGetSymbolAddress((void**)&v16, g_v16);
    cudaGetSymbolAddress((void**)&vt16, g_vt16);
    cudaGetSymbolAddress((void**)&ahi, g_ahi);
    cudaGetSymbolAddress((void**)&alo, g_alo);
    cudaGetSymbolAddress((void**)&w16, g_w16);

    cudaFuncSetAttribute(gemm_f16x2_kernel,
                         cudaFuncAttributeMaxDynamicSharedMemorySize, GEMM_SMEM_BYTES);
    cudaFuncSetAttribute(attn_mma_kernel,
                         cudaFuncAttributeMaxDynamicSharedMemorySize, ATTN_SMEM);

    const size_t WSZ = (size_t)HID * HID;
    const int n4 = MTOT * HID / 4;
    const dim3 cgrid(n4 / 256);
    const dim3 wgrid(HID / 64, HID / 64);
    const dim3 ggrid(HID / BN, MTOT / BM);
    const dim3 blk(256);

    convert_hilo_kernel<<<cgrid, blk>>>(X, xhi, xlo, n4);
    convert_wt_kernel<<<wgrid, blk>>>(Wq, w16 + 0 * WSZ);
    convert_wt_kernel<<<wgrid, blk>>>(Wk, w16 + 1 * WSZ);
    convert_wt_kernel<<<wgrid, blk>>>(Wv, w16 + 2 * WSZ);
    convert_wt_kernel<<<wgrid, blk>>>(Wo, w16 + 3 * WSZ);

    gemm_f16x2_kernel<<<ggrid, blk, GEMM_SMEM_BYTES>>>(
        xhi, xlo, w16 + 0 * WSZ, bq, nullptr, qhi, qlo, 1);
    gemm_f16x2_kernel<<<ggrid, blk, GEMM_SMEM_BYTES>>>(
        xhi, xlo, w16 + 1 * WSZ, bk, nullptr, k16, nullptr, 2);
    gemm_f16x2_kernel<<<ggrid, blk, GEMM_SMEM_BYTES>>>(
        xhi, xlo, w16 + 2 * WSZ, bv, nullptr, v16, nullptr, 2);

    vtrans_kernel<<<dim3(SEQ / 64, HD / 64, BATCH * NHEADS), blk>>>(v16, vt16);

    attn_mma_kernel<<<dim3(SEQ / 128, BATCH * NHEADS), blk, ATTN_SMEM>>>(
        qhi, qlo, k16, vt16, ahi, alo);

    gemm_f16x2_kernel<<<ggrid, blk, GEMM_SMEM_BYTES>>>(
        ahi, alo, w16 + 3 * WSZ, bo, out, nullptr, nullptr, 0);
}

// round 13
// speedup vs baseline: 5.6021x; 1.1482x over previous
#include <cuda_runtime.h>
#include <cuda_fp16.h>
#include <cstdint>

#define HID    2048
#define NHEADS 16
#define HD     128
#define BATCH  2
#define SEQ    2048
#define MTOT   (BATCH * SEQ)   // 4096

// ---------------------------------------------------------------------------
// Scratch (static device arrays; no cudaMalloc anywhere)
// ---------------------------------------------------------------------------
__device__ __half g_xhi[(size_t)MTOT * HID];
__device__ __half g_xlo[(size_t)MTOT * HID];
__device__ __half g_qhi[(size_t)MTOT * HID];
__device__ __half g_qlo[(size_t)MTOT * HID];
__device__ __half g_k16[(size_t)MTOT * HID];
__device__ __half g_vt16[(size_t)MTOT * HID];   // [b,h,d,s]
__device__ __half g_ahi[(size_t)MTOT * HID];
__device__ __half g_alo[(size_t)MTOT * HID];
__device__ __half g_w16[4][(size_t)HID * HID];  // [N][K] transposed fp16

// ---------------------------------------------------------------------------
// PTX helpers — base-target-safe only (no tcgen05 at compute_103)
// ---------------------------------------------------------------------------
static __device__ __forceinline__ uint32_t smem_u32(const void* p) {
    return (uint32_t)__cvta_generic_to_shared(p);
}

#define CP_ASYNC16(dst, src) \
    asm volatile("cp.async.cg.shared.global [%0], [%1], 16;" \
        :: "r"(dst), "l"(src) : "memory")
#define CP_COMMIT() asm volatile("cp.async.commit_group;" ::: "memory")
#define CP_WAIT_1() asm volatile("cp.async.wait_group 1;" ::: "memory")
#define CP_WAIT_0() asm volatile("cp.async.wait_group 0;" ::: "memory")

#define LDSM_X4(r0, r1, r2, r3, addr) \
    asm volatile("ldmatrix.sync.aligned.m8n8.x4.shared.b16 {%0,%1,%2,%3}, [%4];" \
        : "=r"(r0), "=r"(r1), "=r"(r2), "=r"(r3) : "r"(addr))

// mma m16n8k16 row.col fp16 -> f32
#define MMA_F16(c, a, b0, b1) \
    asm volatile("mma.sync.aligned.m16n8k16.row.col.f32.f16.f16.f32 " \
        "{%0,%1,%2,%3}, {%4,%5,%6,%7}, {%8,%9}, {%0,%1,%2,%3};" \
        : "+f"((c)[0]), "+f"((c)[1]), "+f"((c)[2]), "+f"((c)[3]) \
        : "r"((a)[0]), "r"((a)[1]), "r"((a)[2]), "r"((a)[3]), "r"(b0), "r"(b1))

// fast 2^y on the FMA pipe (avoids MUFU throughput ceiling)
static __device__ __forceinline__ float fast_exp2(float y) {
    y = fmaxf(y, -80.f);
    float fl = floorf(y);
    float f = y - fl;
    float p = 0.0013333558f;
    p = fmaf(p, f, 0.0096181291f);
    p = fmaf(p, f, 0.0555041087f);
    p = fmaf(p, f, 0.2402265070f);
    p = fmaf(p, f, 0.6931471806f);
    p = fmaf(p, f, 1.0f);
    int i = (int)fl;
    return p * __int_as_float((i + 127) << 23);
}

// split two fp32 into packed fp16 (hi) + packed fp16 residual (lo)
static __device__ __forceinline__ void split_pack_h(
    float v0, float v1, uint32_t& hi, uint32_t& lo)
{
    const __half h0 = __float2half_rn(v0), h1 = __float2half_rn(v1);
    const __half l0 = __float2half_rn(v0 - __half2float(h0));
    const __half l1 = __float2half_rn(v1 - __half2float(h1));
    __align__(4) __half hh[2] = {h0, h1};
    __align__(4) __half ll[2] = {l0, l1};
    hi = *(const uint32_t*)hh;
    lo = *(const uint32_t*)ll;
}

// ---------------------------------------------------------------------------
// Convert: fp32 -> (fp16 hi, fp16 lo), elementwise (for X)
// ---------------------------------------------------------------------------
__global__ __launch_bounds__(256) void convert_hilo_kernel(
    const float* __restrict__ X, __half* __restrict__ hi,
    __half* __restrict__ lo, int n4)
{
    int i = blockIdx.x * blockDim.x + threadIdx.x;
    if (i >= n4) return;
    float4 v = ((const float4*)X)[i];
    float xs[4] = {v.x, v.y, v.z, v.w};
    __align__(8) __half h[4], l[4];
#pragma unroll
    for (int j = 0; j < 4; ++j) {
        h[j] = __float2half_rn(xs[j]);
        l[j] = __float2half_rn(xs[j] - __half2float(h[j]));
    }
    ((uint2*)hi)[i] = *(const uint2*)h;
    ((uint2*)lo)[i] = *(const uint2*)l;
}

// ---------------------------------------------------------------------------
// Convert + transpose, 4 weights in one launch (z selects the matrix):
//   W fp32 [K,N] -> fp16 [N,K]
// ---------------------------------------------------------------------------
__global__ __launch_bounds__(256) void convert_w4_kernel(
    const float* __restrict__ W0, const float* __restrict__ W1,
    const float* __restrict__ W2, const float* __restrict__ W3,
    __half* __restrict__ w16)
{
    __shared__ float sm[64][65];
    const int k0 = blockIdx.y * 64, n0 = blockIdx.x * 64;
    const int z = blockIdx.z;
    const int tid = threadIdx.x;
    const float* W = (z == 0) ? W0 : (z == 1) ? W1 : (z == 2) ? W2 : W3;
    __half* dst = w16 + (size_t)z * HID * HID;

#pragma unroll
    for (int i = 0; i < 4; ++i) {
        int id = tid + i * 256;
        int r = id >> 4, g = id & 15;
        float4 v = *(const float4*)(W + (size_t)(k0 + r) * HID + n0 + g * 4);
        sm[r][g * 4 + 0] = v.x; sm[r][g * 4 + 1] = v.y;
        sm[r][g * 4 + 2] = v.z; sm[r][g * 4 + 3] = v.w;
    }
    __syncthreads();
#pragma unroll
    for (int i = 0; i < 4; ++i) {
        int id = tid + i * 256;
        int r = id >> 4, g = id & 15;
        __align__(8) __half h[4];
#pragma unroll
        for (int j = 0; j < 4; ++j)
            h[j] = __float2half_rn(sm[g * 4 + j][r]);
        *(uint2*)(dst + (size_t)(n0 + r) * HID + k0 + g * 4) = *(const uint2*)h;
    }
}

// ---------------------------------------------------------------------------
// 2-pass fp16 tensor-core GEMM: C[4096,2048] = (Ahi+Alo) @ B^T + bias
//   A split exact fp16 hi/lo [M,K]; B single fp16 [N,K] (pre-transposed).
// fused==1 (grid.z==3): z=0 -> Q hi/lo head-split [b,h,s,d]
//                       z=1 -> K single fp16 head-split [b,h,s,d]
//                       z=2 -> V single fp16 TRANSPOSED [b,h,d,s]
// fused==0 (grid.z==1): fp32 [M,HID] out (final projection), uses B0/bias0
// BK=64 (halved sync count), cp.async double-buffered.
// ---------------------------------------------------------------------------
#define BM 128
#define BN 128
#define BK 64
#define KT (HID / BK)          // 32
#define ROWB 144               // 64 fp16 = 128B + 16B pad (conflict-free LDSM)
#define TILE_B (128 * ROWB)    // 18432
#define STAGE_B (3 * TILE_B)   // 55296: Ahi, Alo, B
#define GEMM_SMEM_BYTES (2 * STAGE_B)  // 110592

static __device__ __forceinline__ void load_stage(
    const __half* __restrict__ Ahi, const __half* __restrict__ Alo,
    const __half* __restrict__ B16,
    int bm, int bn, int k0, uint32_t s_base, int tid)
{
#pragma unroll
    for (int mat = 0; mat < 3; ++mat) {
        const __half* base = (mat == 0 ? Ahi : mat == 1 ? Alo : B16);
        const int gbase = (mat < 2 ? bm : bn);
#pragma unroll
        for (int i = 0; i < 4; ++i) {
            const int idx = tid + i * 256;     // 0..1023
            const int row = idx >> 3;          // 0..127
            const int ch  = idx & 7;           // 16B chunk (8 per 128B row)
            const __half* src = base + (size_t)(gbase + row) * HID + k0 + ch * 8;
            const uint32_t dst = s_base + mat * TILE_B + row * ROWB + ch * 16;
            CP_ASYNC16(dst, src);
        }
    }
}

__global__ __launch_bounds__(256) void gemm_f16x2_kernel(
    const __half* __restrict__ Ahi, const __half* __restrict__ Alo,
    const __half* __restrict__ B0, const __half* __restrict__ B1,
    const __half* __restrict__ B2,
    const float* __restrict__ bias0, const float* __restrict__ bias1,
    const float* __restrict__ bias2,
    float* __restrict__ Cf,
    __half* __restrict__ Qhi, __half* __restrict__ Qlo,
    __half* __restrict__ K16, __half* __restrict__ Vt16, int fused)
{
    extern __shared__ char smc[];
    const uint32_t s_base = smem_u32(smc);
    const int tid  = threadIdx.x;
    const int wid  = tid >> 5, lane = tid & 31;
    const int wm   = wid & 1, wn = wid >> 1;
    const int m_base = wm * 64, n_base = wn * 32;
    const int bm = blockIdx.y * BM, bn = blockIdx.x * BN;
    const int z = blockIdx.z;
    const __half* B16 = (z == 0) ? B0 : (z == 1) ? B1 : B2;
    const float* bias = (z == 0) ? bias0 : (z == 1) ? bias1 : bias2;

    float c[4][4][4];
#pragma unroll
    for (int i = 0; i < 4; ++i)
#pragma unroll
        for (int j = 0; j < 4; ++j)
#pragma unroll
            for (int r = 0; r < 4; ++r) c[i][j][r] = 0.f;

    const int a_r = lane & 15;
    const int a_c = (lane & 16) ? 8 : 0;
    const int b_r = (lane & 7) + ((lane & 16) ? 8 : 0);
    const int b_c = (lane & 8) ? 8 : 0;

    load_stage(Ahi, Alo, B16, bm, bn, 0, s_base, tid);
    CP_COMMIT();

    for (int t = 0; t < KT; ++t) {
        if (t + 1 < KT) {
            load_stage(Ahi, Alo, B16, bm, bn, (t + 1) * BK,
                       s_base + ((t + 1) & 1) * STAGE_B, tid);
            CP_COMMIT();
            CP_WAIT_1();
        } else {
            CP_WAIT_0();
        }
        __syncthreads();

        const uint32_t sb  = s_base + (t & 1) * STAGE_B;
        const uint32_t sAh = sb;
        const uint32_t sAl = sb + TILE_B;
        const uint32_t sB  = sb + 2 * TILE_B;

#pragma unroll
        for (int ks = 0; ks < 4; ++ks) {
            const int kofs = ks * 16;
            uint32_t ah[4][4], al[4][4], bh[2][4];
#pragma unroll
            for (int mf = 0; mf < 4; ++mf) {
                const uint32_t ra = (uint32_t)((m_base + mf * 16 + a_r) * ROWB
                                               + (kofs + a_c) * 2);
                LDSM_X4(ah[mf][0], ah[mf][1], ah[mf][2], ah[mf][3], sAh + ra);
                LDSM_X4(al[mf][0], al[mf][1], al[mf][2], al[mf][3], sAl + ra);
            }
#pragma unroll
            for (int nb = 0; nb < 2; ++nb) {
                const uint32_t rb = (uint32_t)((n_base + nb * 16 + b_r) * ROWB
                                               + (kofs + b_c) * 2);
                LDSM_X4(bh[nb][0], bh[nb][1], bh[nb][2], bh[nb][3], sB + rb);
            }
#pragma unroll
            for (int mf = 0; mf < 4; ++mf)
#pragma unroll
                for (int nf = 0; nf < 4; ++nf) {
                    const int nb = nf >> 1, sel = (nf & 1) * 2;
                    MMA_F16(c[mf][nf], ah[mf], bh[nb][sel], bh[nb][sel + 1]);
                    MMA_F16(c[mf][nf], al[mf], bh[nb][sel], bh[nb][sel + 1]);
                }
        }
        __syncthreads();
    }

    const int g = lane >> 2, t4 = lane & 3;
#pragma unroll
    for (int mf = 0; mf < 4; ++mf) {
#pragma unroll
        for (int nf = 0; nf < 4; ++nf) {
            const int cb = bn + n_base + nf * 8 + t4 * 2;
            const float bv0 = bias[cb], bv1 = bias[cb + 1];
#pragma unroll
            for (int half = 0; half < 2; ++half) {
                const int row = bm + m_base + mf * 16 + g + half * 8;
                const float v0 = c[mf][nf][half * 2 + 0] + bv0;
                const float v1 = c[mf][nf][half * 2 + 1] + bv1;
                if (!fused) {
                    float2 v; v.x = v0; v.y = v1;
                    *(float2*)(Cf + (size_t)row * HID + cb) = v;
                } else {
                    const int b = row >> 11, s = row & 2047;
                    const int h = cb >> 7, d = cb & 127;
                    if (z == 0) {
                        const size_t off = (((size_t)(b * NHEADS + h)) * SEQ + s) * HD + d;
                        uint32_t hi, lo;
                        split_pack_h(v0, v1, hi, lo);
                        *(uint32_t*)(Qhi + off) = hi;
                        *(uint32_t*)(Qlo + off) = lo;
                    } else if (z == 1) {
                        const size_t off = (((size_t)(b * NHEADS + h)) * SEQ + s) * HD + d;
                        __align__(4) __half hh[2] = {__float2half_rn(v0), __float2half_rn(v1)};
                        *(uint32_t*)(K16 + off) = *(const uint32_t*)hh;
                    } else {
                        // V transposed: [b,h,d,s]
                        const size_t tb = ((size_t)(b * NHEADS + h)) * HD;
                        Vt16[(tb + d) * SEQ + s]     = __float2half_rn(v0);
                        Vt16[(tb + d + 1) * SEQ + s] = __float2half_rn(v1);
                    }
                }
            }
        }
    }
}

// ---------------------------------------------------------------------------
// Flash attention, fp16 2-pass mma.sync, online softmax (log2 domain)
// CTA: 128 Q rows x one (b,h). KV chunks of 64, cp.async double-buffered.
//   scores = (Qhi + Qlo) . K16;  O = (Phi + Plo) . V16
// ---------------------------------------------------------------------------
#define AT_QROW 272
#define AT_KROW 272
#define AT_VROW 144
#define AT_QHI 0
#define AT_QLO 34816
#define AT_STAGE0 69632
#define AT_K 0
#define AT_V 17408
#define AT_STAGEB 35840
#define ATTN_SMEM (AT_STAGE0 + 2 * AT_STAGEB)   // 141312

static __device__ __forceinline__ void attn_load_kv(
    const __half* __restrict__ K16, const __half* __restrict__ Vt16,
    size_t hbase, size_t vbase, int kv0, uint32_t stage, int tid)
{
#pragma unroll
    for (int i = 0; i < 4; ++i) {
        const int idx = tid + i * 256;         // 0..1023
        const int r  = idx >> 4, ch = idx & 15;
        CP_ASYNC16(stage + AT_K + r * AT_KROW + ch * 16,
                   K16 + hbase + (size_t)(kv0 + r) * HD + ch * 8);
        const int vr = idx >> 3, vch = idx & 7;
        CP_ASYNC16(stage + AT_V + vr * AT_VROW + vch * 16,
                   Vt16 + vbase + (size_t)vr * SEQ + kv0 + vch * 8);
    }
}

__global__ __launch_bounds__(256) void attn_mma_kernel(
    const __half* __restrict__ Qhi, const __half* __restrict__ Qlo,
    const __half* __restrict__ K16, const __half* __restrict__ Vt16,
    __half* __restrict__ Ohi, __half* __restrict__ Olo)
{
    extern __shared__ char smc[];
    const uint32_t sb = smem_u32(smc);
    const int tid = threadIdx.x, wid = tid >> 5, lane = tid & 31;
    const int bh = blockIdx.y, qt = blockIdx.x;
    const int g = lane >> 2, t4 = lane & 3;
    const int wm = wid * 16;
    const float CSCL = 0.12751743f;   // (1/sqrt(128)) * log2(e)

    const size_t hbase = (size_t)bh * SEQ * HD;
    const size_t vbase = (size_t)bh * HD * SEQ;
    const int s0 = qt * 128;

    // Q tile hi/lo (persistent in smem)
#pragma unroll
    for (int i = 0; i < 8; ++i) {
        const int idx = tid + i * 256;
        const int r = idx >> 4, ch = idx & 15;
        CP_ASYNC16(sb + AT_QHI + r * AT_QROW + ch * 16,
                   Qhi + hbase + (size_t)(s0 + r) * HD + ch * 8);
        CP_ASYNC16(sb + AT_QLO + r * AT_QROW + ch * 16,
                   Qlo + hbase + (size_t)(s0 + r) * HD + ch * 8);
    }
    attn_load_kv(K16, Vt16, hbase, vbase, 0, sb + AT_STAGE0, tid);
    CP_COMMIT();
    attn_load_kv(K16, Vt16, hbase, vbase, 64, sb + AT_STAGE0 + AT_STAGEB, tid);
    CP_COMMIT();

    float o[16][4];
#pragma unroll
    for (int nf = 0; nf < 16; ++nf)
#pragma unroll
        for (int r = 0; r < 4; ++r) o[nf][r] = 0.f;
    float m0 = -1e30f, m1 = -1e30f, l0 = 0.f, l1 = 0.f;

    const int a_r = lane & 15;
    const int a_c = (lane & 16) ? 8 : 0;
    const int b_r = (lane & 7) + ((lane & 16) ? 8 : 0);
    const int b_c = (lane & 8) ? 8 : 0;

    for (int t = 0; t < SEQ / 64; ++t) {
        if (t < SEQ / 64 - 1) { CP_WAIT_1(); } else { CP_WAIT_0(); }
        __syncthreads();
        const uint32_t st = sb + AT_STAGE0 + (t & 1) * AT_STAGEB;

        // ---- scores = Q K^T (2-pass: Qhi + Qlo)
        float sc[8][4];
#pragma unroll
        for (int nf = 0; nf < 8; ++nf)
#pragma unroll
            for (int r = 0; r < 4; ++r) sc[nf][r] = 0.f;

#pragma unroll
        for (int kb = 0; kb < 8; ++kb) {
            uint32_t qh[4], ql[4];
            const uint32_t qa = sb + AT_QHI + (wm + a_r) * AT_QROW + (kb * 16 + a_c) * 2;
            LDSM_X4(qh[0], qh[1], qh[2], qh[3], qa);
            LDSM_X4(ql[0], ql[1], ql[2], ql[3], qa + (AT_QLO - AT_QHI));
#pragma unroll
            for (int nb = 0; nb < 4; ++nb) {
                uint32_t kh[4];
                const uint32_t ka = st + AT_K + (nb * 16 + b_r) * AT_KROW
                                    + (kb * 16 + b_c) * 2;
                LDSM_X4(kh[0], kh[1], kh[2], kh[3], ka);
                MMA_F16(sc[2 * nb],     qh, kh[0], kh[1]);
                MMA_F16(sc[2 * nb],     ql, kh[0], kh[1]);
                MMA_F16(sc[2 * nb + 1], qh, kh[2], kh[3]);
                MMA_F16(sc[2 * nb + 1], ql, kh[2], kh[3]);
            }
        }

        // ---- online softmax (base-2)
        float mx0 = -1e30f, mx1 = -1e30f;
#pragma unroll
        for (int nf = 0; nf < 8; ++nf) {
            sc[nf][0] *= CSCL; sc[nf][1] *= CSCL;
            sc[nf][2] *= CSCL; sc[nf][3] *= CSCL;
            mx0 = fmaxf(mx0, fmaxf(sc[nf][0], sc[nf][1]));
            mx1 = fmaxf(mx1, fmaxf(sc[nf][2], sc[nf][3]));
        }
        mx0 = fmaxf(mx0, __shfl_xor_sync(0xffffffffu, mx0, 1));
        mx0 = fmaxf(mx0, __shfl_xor_sync(0xffffffffu, mx0, 2));
        mx1 = fmaxf(mx1, __shfl_xor_sync(0xffffffffu, mx1, 1));
        mx1 = fmaxf(mx1, __shfl_xor_sync(0xffffffffu, mx1, 2));
        const float mn0 = fmaxf(m0, mx0), mn1 = fmaxf(m1, mx1);
        const float cr0 = fast_exp2(m0 - mn0), cr1 = fast_exp2(m1 - mn1);
        m0 = mn0; m1 = mn1;
        float rs0 = 0.f, rs1 = 0.f;
#pragma unroll
        for (int nf = 0; nf < 8; ++nf) {
            sc[nf][0] = fast_exp2(sc[nf][0] - mn0);
            sc[nf][1] = fast_exp2(sc[nf][1] - mn0);
            sc[nf][2] = fast_exp2(sc[nf][2] - mn1);
            sc[nf][3] = fast_exp2(sc[nf][3] - mn1);
            rs0 += sc[nf][0] + sc[nf][1];
            rs1 += sc[nf][2] + sc[nf][3];
        }
        rs0 += __shfl_xor_sync(0xffffffffu, rs0, 1);
        rs0 += __shfl_xor_sync(0xffffffffu, rs0, 2);
        rs1 += __shfl_xor_sync(0xffffffffu, rs1, 1);
        rs1 += __shfl_xor_sync(0xffffffffu, rs1, 2);
        l0 = l0 * cr0 + rs0;
        l1 = l1 * cr1 + rs1;
#pragma unroll
        for (int nf = 0; nf < 16; ++nf) {
            o[nf][0] *= cr0; o[nf][1] *= cr0;
            o[nf][2] *= cr1; o[nf][3] *= cr1;
        }

        // ---- O += P V (P split fp16 hi/lo; V^T single fp16)
#pragma unroll
        for (int kb = 0; kb < 4; ++kb) {
            uint32_t pah[4], pal[4];
#pragma unroll
            for (int jj = 0; jj < 2; ++jj) {
                const int j = 2 * kb + jj;
                split_pack_h(sc[j][0], sc[j][1], pah[2 * jj], pal[2 * jj]);
                split_pack_h(sc[j][2], sc[j][3], pah[2 * jj + 1], pal[2 * jj + 1]);
            }
#pragma unroll
            for (int nb = 0; nb < 8; ++nb) {
                uint32_t vh[4];
                const uint32_t va = st + AT_V + (nb * 16 + b_r) * AT_VROW
                                    + (kb * 16 + b_c) * 2;
                LDSM_X4(vh[0], vh[1], vh[2], vh[3], va);
                MMA_F16(o[2 * nb],     pah, vh[0], vh[1]);
                MMA_F16(o[2 * nb],     pal, vh[0], vh[1]);
                MMA_F16(o[2 * nb + 1], pah, vh[2], vh[3]);
                MMA_F16(o[2 * nb + 1], pal, vh[2], vh[3]);
            }
        }
        __syncthreads();
        if (t + 2 < SEQ / 64) {
            attn_load_kv(K16, Vt16, hbase, vbase, (t + 2) * 64,
                         sb + AT_STAGE0 + (t & 1) * AT_STAGEB, tid);
            CP_COMMIT();
        }
    }

    // ---- epilogue: normalize, split fp16 hi/lo, write merged [B*S, HID]
    const float inv0 = 1.f / l0, inv1 = 1.f / l1;
    const int b = bh >> 4, h = bh & 15;
    const size_t r0 = (size_t)b * SEQ + s0 + wm + g;
    const size_t r1 = r0 + 8;
#pragma unroll
    for (int nf = 0; nf < 16; ++nf) {
        const int col = h * HD + nf * 8 + t4 * 2;
        uint32_t hi, lo;
        split_pack_h(o[nf][0] * inv0, o[nf][1] * inv0, hi, lo);
        *(uint32_t*)(Ohi + r0 * HID + col) = hi;
        *(uint32_t*)(Olo + r0 * HID + col) = lo;
        split_pack_h(o[nf][2] * inv1, o[nf][3] * inv1, hi, lo);
        *(uint32_t*)(Ohi + r1 * HID + col) = hi;
        *(uint32_t*)(Olo + r1 * HID + col) = lo;
    }
}

// ---------------------------------------------------------------------------
extern "C" void kernel_launch(void* const* d_in, const int* in_sizes, int n_in,
                              void* d_out, int out_size) {
    const float* X  = (const float*)d_in[0];
    const float* Wq = (const float*)d_in[1];
    const float* bq = (const float*)d_in[2];
    const float* Wk = (const float*)d_in[3];
    const float* bk = (const float*)d_in[4];
    const float* Wv = (const float*)d_in[5];
    const float* bv = (const float*)d_in[6];
    const float* Wo = (const float*)d_in[7];
    const float* bo = (const float*)d_in[8];
    float* out = (float*)d_out;

    __half *xhi, *xlo, *qhi, *qlo, *k16, *vt16, *ahi, *alo, *w16;
    cudaGetSymbolAddress((void**)&xhi, g_xhi);
    cudaGetSymbolAddress((void**)&xlo, g_xlo);
    cudaGetSymbolAddress((void**)&qhi, g_qhi);
    cudaGetSymbolAddress((void**)&qlo, g_qlo);
    cudaGetSymbolAddress((void**)&k16, g_k16);
    cudaGetSymbolAddress((void**)&vt16, g_vt16);
    cudaGetSymbolAddress((void**)&ahi, g_ahi);
    cudaGetSymbolAddress((void**)&alo, g_alo);
    cudaGetSymbolAddress((void**)&w16, g_w16);

    cudaFuncSetAttribute(gemm_f16x2_kernel,
                         cudaFuncAttributeMaxDynamicSharedMemorySize, GEMM_SMEM_BYTES);
    cudaFuncSetAttribute(attn_mma_kernel,
                         cudaFuncAttributeMaxDynamicSharedMemorySize, ATTN_SMEM);

    const size_t WSZ = (size_t)HID * HID;
    const int n4 = MTOT * HID / 4;
    const dim3 blk(256);

    // X -> fp16 hi/lo; all 4 weights -> fp16 [N,K] in one launch
    convert_hilo_kernel<<<dim3(n4 / 256), blk>>>(X, xhi, xlo, n4);
    convert_w4_kernel<<<dim3(HID / 64, HID / 64, 4), blk>>>(Wq, Wk, Wv, Wo, w16);

    // Fused Q/K/V projections: one launch, z selects output head-split target
    gemm_f16x2_kernel<<<dim3(HID / BN, MTOT / BM, 3), blk, GEMM_SMEM_BYTES>>>(
        xhi, xlo, w16 + 0 * WSZ, w16 + 1 * WSZ, w16 + 2 * WSZ,
        bq, bk, bv, nullptr, qhi, qlo, k16, vt16, 1);

    // Attention (fp16 2-pass mma)
    attn_mma_kernel<<<dim3(SEQ / 128, BATCH * NHEADS), blk, ATTN_SMEM>>>(
        qhi, qlo, k16, vt16, ahi, alo);

    // Output projection -> fp32 d_out
    gemm_f16x2_kernel<<<dim3(HID / BN, MTOT / BM, 1), blk, GEMM_SMEM_BYTES>>>(
        ahi, alo, w16 + 3 * WSZ, nullptr, nullptr,
        bo, nullptr, nullptr, out, nullptr, nullptr, nullptr, nullptr, 0);
}

// round 15
// speedup vs baseline: 5.9728x; 1.0662x over previous
#include <cuda_runtime.h>
#include <cuda_fp16.h>
#include <cstdint>

#define HID    2048
#define NHEADS 16
#define HD     128
#define BATCH  2
#define SEQ    2048
#define MTOT   (BATCH * SEQ)   // 4096

// ---------------------------------------------------------------------------
// Scratch (static device arrays; no cudaMalloc anywhere)
// ---------------------------------------------------------------------------
__device__ __half g_xhi[(size_t)MTOT * HID];
__device__ __half g_xlo[(size_t)MTOT * HID];
__device__ __half g_qhi[(size_t)MTOT * HID];
__device__ __half g_qlo[(size_t)MTOT * HID];
__device__ __half g_k16[(size_t)MTOT * HID];
__device__ __half g_vt16[(size_t)MTOT * HID];   // [b,h,d,s]
__device__ __half g_ahi[(size_t)MTOT * HID];
__device__ __half g_alo[(size_t)MTOT * HID];
__device__ __half g_w16[4][(size_t)HID * HID];  // [N][K] transposed fp16

// ---------------------------------------------------------------------------
// PTX helpers — base-target-safe only (no tcgen05 at compute_103)
// ---------------------------------------------------------------------------
static __device__ __forceinline__ uint32_t smem_u32(const void* p) {
    return (uint32_t)__cvta_generic_to_shared(p);
}

#define CP_ASYNC16(dst, src) \
    asm volatile("cp.async.cg.shared.global [%0], [%1], 16;" \
        :: "r"(dst), "l"(src) : "memory")
#define CP_COMMIT() asm volatile("cp.async.commit_group;" ::: "memory")
#define CP_WAIT_1() asm volatile("cp.async.wait_group 1;" ::: "memory")
#define CP_WAIT_0() asm volatile("cp.async.wait_group 0;" ::: "memory")

#define LDSM_X4(r0, r1, r2, r3, addr) \
    asm volatile("ldmatrix.sync.aligned.m8n8.x4.shared.b16 {%0,%1,%2,%3}, [%4];" \
        : "=r"(r0), "=r"(r1), "=r"(r2), "=r"(r3) : "r"(addr))

// mma m16n8k16 row.col fp16 -> f32
#define MMA_F16(c, a, b0, b1) \
    asm volatile("mma.sync.aligned.m16n8k16.row.col.f32.f16.f16.f32 " \
        "{%0,%1,%2,%3}, {%4,%5,%6,%7}, {%8,%9}, {%0,%1,%2,%3};" \
        : "+f"((c)[0]), "+f"((c)[1]), "+f"((c)[2]), "+f"((c)[3]) \
        : "r"((a)[0]), "r"((a)[1]), "r"((a)[2]), "r"((a)[3]), "r"(b0), "r"(b1))

// fast 2^y on the FMA pipe (avoids MUFU throughput ceiling)
static __device__ __forceinline__ float fast_exp2(float y) {
    y = fmaxf(y, -80.f);
    float fl = floorf(y);
    float f = y - fl;
    float p = 0.0013333558f;
    p = fmaf(p, f, 0.0096181291f);
    p = fmaf(p, f, 0.0555041087f);
    p = fmaf(p, f, 0.2402265070f);
    p = fmaf(p, f, 0.6931471806f);
    p = fmaf(p, f, 1.0f);
    int i = (int)fl;
    return p * __int_as_float((i + 127) << 23);
}

// split two fp32 into packed fp16 (hi) + packed fp16 residual (lo)
static __device__ __forceinline__ void split_pack_h(
    float v0, float v1, uint32_t& hi, uint32_t& lo)
{
    const __half h0 = __float2half_rn(v0), h1 = __float2half_rn(v1);
    const __half l0 = __float2half_rn(v0 - __half2float(h0));
    const __half l1 = __float2half_rn(v1 - __half2float(h1));
    __align__(4) __half hh[2] = {h0, h1};
    __align__(4) __half ll[2] = {l0, l1};
    hi = *(const uint32_t*)hh;
    lo = *(const uint32_t*)ll;
}

// ---------------------------------------------------------------------------
// Convert: fp32 -> (fp16 hi, fp16 lo), elementwise (for X)
// ---------------------------------------------------------------------------
__global__ __launch_bounds__(256) void convert_hilo_kernel(
    const float* __restrict__ X, __half* __restrict__ hi,
    __half* __restrict__ lo, int n4)
{
    int i = blockIdx.x * blockDim.x + threadIdx.x;
    if (i >= n4) return;
    float4 v = ((const float4*)X)[i];
    float xs[4] = {v.x, v.y, v.z, v.w};
    __align__(8) __half h[4], l[4];
#pragma unroll
    for (int j = 0; j < 4; ++j) {
        h[j] = __float2half_rn(xs[j]);
        l[j] = __float2half_rn(xs[j] - __half2float(h[j]));
    }
    ((uint2*)hi)[i] = *(const uint2*)h;
    ((uint2*)lo)[i] = *(const uint2*)l;
}

// ---------------------------------------------------------------------------
// Convert + transpose, 4 weights in one launch (z selects the matrix):
//   W fp32 [K,N] -> fp16 [N,K]
// ---------------------------------------------------------------------------
__global__ __launch_bounds__(256) void convert_w4_kernel(
    const float* __restrict__ W0, const float* __restrict__ W1,
    const float* __restrict__ W2, const float* __restrict__ W3,
    __half* __restrict__ w16)
{
    __shared__ float sm[64][65];
    const int k0 = blockIdx.y * 64, n0 = blockIdx.x * 64;
    const int z = blockIdx.z;
    const int tid = threadIdx.x;
    const float* W = (z == 0) ? W0 : (z == 1) ? W1 : (z == 2) ? W2 : W3;
    __half* dst = w16 + (size_t)z * HID * HID;

#pragma unroll
    for (int i = 0; i < 4; ++i) {
        int id = tid + i * 256;
        int r = id >> 4, g = id & 15;
        float4 v = *(const float4*)(W + (size_t)(k0 + r) * HID + n0 + g * 4);
        sm[r][g * 4 + 0] = v.x; sm[r][g * 4 + 1] = v.y;
        sm[r][g * 4 + 2] = v.z; sm[r][g * 4 + 3] = v.w;
    }
    __syncthreads();
#pragma unroll
    for (int i = 0; i < 4; ++i) {
        int id = tid + i * 256;
        int r = id >> 4, g = id & 15;
        __align__(8) __half h[4];
#pragma unroll
        for (int j = 0; j < 4; ++j)
            h[j] = __float2half_rn(sm[g * 4 + j][r]);
        *(uint2*)(dst + (size_t)(n0 + r) * HID + k0 + g * 4) = *(const uint2*)h;
    }
}

// ---------------------------------------------------------------------------
// 2-pass fp16 tensor-core GEMM: C[4096,2048] = (Ahi+Alo) @ B^T + bias
// fused==1 (grid.z==3): z=0 -> Q hi/lo head-split; z=1 -> K fp16; z=2 -> V^T
// fused==0: fp32 [M,HID] out
// ---------------------------------------------------------------------------
#define BM 128
#define BN 128
#define BK 64
#define KT (HID / BK)          // 32
#define ROWB 144               // 64 fp16 = 128B + 16B pad (conflict-free LDSM)
#define TILE_B (128 * ROWB)    // 18432
#define STAGE_B (3 * TILE_B)   // 55296: Ahi, Alo, B
#define GEMM_SMEM_BYTES (2 * STAGE_B)  // 110592

static __device__ __forceinline__ void load_stage(
    const __half* __restrict__ Ahi, const __half* __restrict__ Alo,
    const __half* __restrict__ B16,
    int bm, int bn, int k0, uint32_t s_base, int tid)
{
#pragma unroll
    for (int mat = 0; mat < 3; ++mat) {
        const __half* base = (mat == 0 ? Ahi : mat == 1 ? Alo : B16);
        const int gbase = (mat < 2 ? bm : bn);
#pragma unroll
        for (int i = 0; i < 4; ++i) {
            const int idx = tid + i * 256;     // 0..1023
            const int row = idx >> 3;          // 0..127
            const int ch  = idx & 7;           // 16B chunk (8 per 128B row)
            const __half* src = base + (size_t)(gbase + row) * HID + k0 + ch * 8;
            const uint32_t dst = s_base + mat * TILE_B + row * ROWB + ch * 16;
            CP_ASYNC16(dst, src);
        }
    }
}

__global__ __launch_bounds__(256) void gemm_f16x2_kernel(
    const __half* __restrict__ Ahi, const __half* __restrict__ Alo,
    const __half* __restrict__ B0, const __half* __restrict__ B1,
    const __half* __restrict__ B2,
    const float* __restrict__ bias0, const float* __restrict__ bias1,
    const float* __restrict__ bias2,
    float* __restrict__ Cf,
    __half* __restrict__ Qhi, __half* __restrict__ Qlo,
    __half* __restrict__ K16, __half* __restrict__ Vt16, int fused)
{
    extern __shared__ char smc[];
    const uint32_t s_base = smem_u32(smc);
    const int tid  = threadIdx.x;
    const int wid  = tid >> 5, lane = tid & 31;
    const int wm   = wid & 1, wn = wid >> 1;
    const int m_base = wm * 64, n_base = wn * 32;
    const int bm = blockIdx.y * BM, bn = blockIdx.x * BN;
    const int z = blockIdx.z;
    const __half* B16 = (z == 0) ? B0 : (z == 1) ? B1 : B2;
    const float* bias = (z == 0) ? bias0 : (z == 1) ? bias1 : bias2;

    float c[4][4][4];
#pragma unroll
    for (int i = 0; i < 4; ++i)
#pragma unroll
        for (int j = 0; j < 4; ++j)
#pragma unroll
            for (int r = 0; r < 4; ++r) c[i][j][r] = 0.f;

    const int a_r = lane & 15;
    const int a_c = (lane & 16) ? 8 : 0;
    const int b_r = (lane & 7) + ((lane & 16) ? 8 : 0);
    const int b_c = (lane & 8) ? 8 : 0;

    load_stage(Ahi, Alo, B16, bm, bn, 0, s_base, tid);
    CP_COMMIT();

    for (int t = 0; t < KT; ++t) {
        if (t + 1 < KT) {
            load_stage(Ahi, Alo, B16, bm, bn, (t + 1) * BK,
                       s_base + ((t + 1) & 1) * STAGE_B, tid);
            CP_COMMIT();
            CP_WAIT_1();
        } else {
            CP_WAIT_0();
        }
        __syncthreads();

        const uint32_t sb  = s_base + (t & 1) * STAGE_B;
        const uint32_t sAh = sb;
        const uint32_t sAl = sb + TILE_B;
        const uint32_t sB  = sb + 2 * TILE_B;

#pragma unroll
        for (int ks = 0; ks < 4; ++ks) {
            const int kofs = ks * 16;
            uint32_t ah[4][4], al[4][4], bh[2][4];
#pragma unroll
            for (int mf = 0; mf < 4; ++mf) {
                const uint32_t ra = (uint32_t)((m_base + mf * 16 + a_r) * ROWB
                                               + (kofs + a_c) * 2);
                LDSM_X4(ah[mf][0], ah[mf][1], ah[mf][2], ah[mf][3], sAh + ra);
                LDSM_X4(al[mf][0], al[mf][1], al[mf][2], al[mf][3], sAl + ra);
            }
#pragma unroll
            for (int nb = 0; nb < 2; ++nb) {
                const uint32_t rb = (uint32_t)((n_base + nb * 16 + b_r) * ROWB
                                               + (kofs + b_c) * 2);
                LDSM_X4(bh[nb][0], bh[nb][1], bh[nb][2], bh[nb][3], sB + rb);
            }
#pragma unroll
            for (int mf = 0; mf < 4; ++mf)
#pragma unroll
                for (int nf = 0; nf < 4; ++nf) {
                    const int nb = nf >> 1, sel = (nf & 1) * 2;
                    MMA_F16(c[mf][nf], ah[mf], bh[nb][sel], bh[nb][sel + 1]);
                    MMA_F16(c[mf][nf], al[mf], bh[nb][sel], bh[nb][sel + 1]);
                }
        }
        __syncthreads();
    }

    const int g = lane >> 2, t4 = lane & 3;
#pragma unroll
    for (int mf = 0; mf < 4; ++mf) {
#pragma unroll
        for (int nf = 0; nf < 4; ++nf) {
            const int cb = bn + n_base + nf * 8 + t4 * 2;
            const float bv0 = bias[cb], bv1 = bias[cb + 1];
#pragma unroll
            for (int half = 0; half < 2; ++half) {
                const int row = bm + m_base + mf * 16 + g + half * 8;
                const float v0 = c[mf][nf][half * 2 + 0] + bv0;
                const float v1 = c[mf][nf][half * 2 + 1] + bv1;
                if (!fused) {
                    float2 v; v.x = v0; v.y = v1;
                    *(float2*)(Cf + (size_t)row * HID + cb) = v;
                } else {
                    const int b = row >> 11, s = row & 2047;
                    const int h = cb >> 7, d = cb & 127;
                    if (z == 0) {
                        const size_t off = (((size_t)(b * NHEADS + h)) * SEQ + s) * HD + d;
                        uint32_t hi, lo;
                        split_pack_h(v0, v1, hi, lo);
                        *(uint32_t*)(Qhi + off) = hi;
                        *(uint32_t*)(Qlo + off) = lo;
                    } else if (z == 1) {
                        const size_t off = (((size_t)(b * NHEADS + h)) * SEQ + s) * HD + d;
                        __align__(4) __half hh[2] = {__float2half_rn(v0), __float2half_rn(v1)};
                        *(uint32_t*)(K16 + off) = *(const uint32_t*)hh;
                    } else {
                        // V transposed: [b,h,d,s]
                        const size_t tb = ((size_t)(b * NHEADS + h)) * HD;
                        Vt16[(tb + d) * SEQ + s]     = __float2half_rn(v0);
                        Vt16[(tb + d + 1) * SEQ + s] = __float2half_rn(v1);
                    }
                }
            }
        }
    }
}

// ---------------------------------------------------------------------------
// Flash attention, fp16 2-pass mma.sync, online softmax (log2 domain)
// CTA: 4 warps, 64 Q rows x one (b,h); 106.5 KB smem -> 2 CTAs/SM so one
// CTA's HMMAs cover the other's softmax bubble. KV chunks of 64, double-buffered.
// ---------------------------------------------------------------------------
#define AT_QROW 272
#define AT_KROW 272
#define AT_VROW 144
#define AT_QHI 0
#define AT_QLO 17408            // 64 * 272
#define AT_STAGE0 34816
#define AT_K 0
#define AT_V 17408
#define AT_STAGEB 35840         // K 17408 + V 18432
#define ATTN_SMEM (AT_STAGE0 + 2 * AT_STAGEB)   // 106496

static __device__ __forceinline__ void attn_load_kv(
    const __half* __restrict__ K16, const __half* __restrict__ Vt16,
    size_t hbase, size_t vbase, int kv0, uint32_t stage, int tid)
{
#pragma unroll
    for (int i = 0; i < 8; ++i) {
        const int idx = tid + i * 128;         // 0..1023
        const int r  = idx >> 4, ch = idx & 15;
        CP_ASYNC16(stage + AT_K + r * AT_KROW + ch * 16,
                   K16 + hbase + (size_t)(kv0 + r) * HD + ch * 8);
        const int vr = idx >> 3, vch = idx & 7;
        CP_ASYNC16(stage + AT_V + vr * AT_VROW + vch * 16,
                   Vt16 + vbase + (size_t)vr * SEQ + kv0 + vch * 8);
    }
}

__global__ __launch_bounds__(128, 2) void attn_mma_kernel(
    const __half* __restrict__ Qhi, const __half* __restrict__ Qlo,
    const __half* __restrict__ K16, const __half* __restrict__ Vt16,
    __half* __restrict__ Ohi, __half* __restrict__ Olo)
{
    extern __shared__ char smc[];
    const uint32_t sb = smem_u32(smc);
    const int tid = threadIdx.x, wid = tid >> 5, lane = tid & 31;
    const int bh = blockIdx.y, qt = blockIdx.x;
    const int g = lane >> 2, t4 = lane & 3;
    const int wm = wid * 16;
    const float CSCL = 0.12751743f;   // (1/sqrt(128)) * log2(e)

    const size_t hbase = (size_t)bh * SEQ * HD;
    const size_t vbase = (size_t)bh * HD * SEQ;
    const int s0 = qt * 64;

    // Q tile hi/lo (persistent in smem): 64 rows x 16 chunks per matrix
#pragma unroll
    for (int i = 0; i < 8; ++i) {
        const int idx = tid + i * 128;
        const int r = idx >> 4, ch = idx & 15;
        CP_ASYNC16(sb + AT_QHI + r * AT_QROW + ch * 16,
                   Qhi + hbase + (size_t)(s0 + r) * HD + ch * 8);
        CP_ASYNC16(sb + AT_QLO + r * AT_QROW + ch * 16,
                   Qlo + hbase + (size_t)(s0 + r) * HD + ch * 8);
    }
    attn_load_kv(K16, Vt16, hbase, vbase, 0, sb + AT_STAGE0, tid);
    CP_COMMIT();
    attn_load_kv(K16, Vt16, hbase, vbase, 64, sb + AT_STAGE0 + AT_STAGEB, tid);
    CP_COMMIT();

    float o[16][4];
#pragma unroll
    for (int nf = 0; nf < 16; ++nf)
#pragma unroll
        for (int r = 0; r < 4; ++r) o[nf][r] = 0.f;
    float m0 = -1e30f, m1 = -1e30f, l0 = 0.f, l1 = 0.f;

    const int a_r = lane & 15;
    const int a_c = (lane & 16) ? 8 : 0;
    const int b_r = (lane & 7) + ((lane & 16) ? 8 : 0);
    const int b_c = (lane & 8) ? 8 : 0;

    for (int t = 0; t < SEQ / 64; ++t) {
        if (t < SEQ / 64 - 1) { CP_WAIT_1(); } else { CP_WAIT_0(); }
        __syncthreads();
        const uint32_t st = sb + AT_STAGE0 + (t & 1) * AT_STAGEB;

        // ---- scores = Q K^T (2-pass: Qhi + Qlo)
        float sc[8][4];
#pragma unroll
        for (int nf = 0; nf < 8; ++nf)
#pragma unroll
            for (int r = 0; r < 4; ++r) sc[nf][r] = 0.f;

#pragma unroll
        for (int kb = 0; kb < 8; ++kb) {
            uint32_t qh[4], ql[4];
            const uint32_t qa = sb + AT_QHI + (wm + a_r) * AT_QROW + (kb * 16 + a_c) * 2;
            LDSM_X4(qh[0], qh[1], qh[2], qh[3], qa);
            LDSM_X4(ql[0], ql[1], ql[2], ql[3], qa + (AT_QLO - AT_QHI));
#pragma unroll
            for (int nb = 0; nb < 4; ++nb) {
                uint32_t kh[4];
                const uint32_t ka = st + AT_K + (nb * 16 + b_r) * AT_KROW
                                    + (kb * 16 + b_c) * 2;
                LDSM_X4(kh[0], kh[1], kh[2], kh[3], ka);
                MMA_F16(sc[2 * nb],     qh, kh[0], kh[1]);
                MMA_F16(sc[2 * nb],     ql, kh[0], kh[1]);
                MMA_F16(sc[2 * nb + 1], qh, kh[2], kh[3]);
                MMA_F16(sc[2 * nb + 1], ql, kh[2], kh[3]);
            }
        }

        // ---- online softmax (base-2)
        float mx0 = -1e30f, mx1 = -1e30f;
#pragma unroll
        for (int nf = 0; nf < 8; ++nf) {
            sc[nf][0] *= CSCL; sc[nf][1] *= CSCL;
            sc[nf][2] *= CSCL; sc[nf][3] *= CSCL;
            mx0 = fmaxf(mx0, fmaxf(sc[nf][0], sc[nf][1]));
            mx1 = fmaxf(mx1, fmaxf(sc[nf][2], sc[nf][3]));
        }
        mx0 = fmaxf(mx0, __shfl_xor_sync(0xffffffffu, mx0, 1));
        mx0 = fmaxf(mx0, __shfl_xor_sync(0xffffffffu, mx0, 2));
        mx1 = fmaxf(mx1, __shfl_xor_sync(0xffffffffu, mx1, 1));
        mx1 = fmaxf(mx1, __shfl_xor_sync(0xffffffffu, mx1, 2));
        const float mn0 = fmaxf(m0, mx0), mn1 = fmaxf(m1, mx1);
        const float cr0 = fast_exp2(m0 - mn0), cr1 = fast_exp2(m1 - mn1);
        m0 = mn0; m1 = mn1;
        float rs0 = 0.f, rs1 = 0.f;
#pragma unroll
        for (int nf = 0; nf < 8; ++nf) {
            sc[nf][0] = fast_exp2(sc[nf][0] - mn0);
            sc[nf][1] = fast_exp2(sc[nf][1] - mn0);
            sc[nf][2] = fast_exp2(sc[nf][2] - mn1);
            sc[nf][3] = fast_exp2(sc[nf][3] - mn1);
            rs0 += sc[nf][0] + sc[nf][1];
            rs1 += sc[nf][2] + sc[nf][3];
        }
        rs0 += __shfl_xor_sync(0xffffffffu, rs0, 1);
        rs0 += __shfl_xor_sync(0xffffffffu, rs0, 2);
        rs1 += __shfl_xor_sync(0xffffffffu, rs1, 1);
        rs1 += __shfl_xor_sync(0xffffffffu, rs1, 2);
        l0 = l0 * cr0 + rs0;
        l1 = l1 * cr1 + rs1;
#pragma unroll
        for (int nf = 0; nf < 16; ++nf) {
            o[nf][0] *= cr0; o[nf][1] *= cr0;
            o[nf][2] *= cr1; o[nf][3] *= cr1;
        }

        // ---- O += P V (P split fp16 hi/lo; V^T single fp16)
#pragma unroll
        for (int kb = 0; kb < 4; ++kb) {
            uint32_t pah[4], pal[4];
#pragma unroll
            for (int jj = 0; jj < 2; ++jj) {
                const int j = 2 * kb + jj;
                split_pack_h(sc[j][0], sc[j][1], pah[2 * jj], pal[2 * jj]);
                split_pack_h(sc[j][2], sc[j][3], pah[2 * jj + 1], pal[2 * jj + 1]);
            }
#pragma unroll
            for (int nb = 0; nb < 8; ++nb) {
                uint32_t vh[4];
                const uint32_t va = st + AT_V + (nb * 16 + b_r) * AT_VROW
                                    + (kb * 16 + b_c) * 2;
                LDSM_X4(vh[0], vh[1], vh[2], vh[3], va);
                MMA_F16(o[2 * nb],     pah, vh[0], vh[1]);
                MMA_F16(o[2 * nb],     pal, vh[0], vh[1]);
                MMA_F16(o[2 * nb + 1], pah, vh[2], vh[3]);
                MMA_F16(o[2 * nb + 1], pal, vh[2], vh[3]);
            }
        }
        __syncthreads();
        if (t + 2 < SEQ / 64) {
            attn_load_kv(K16, Vt16, hbase, vbase, (t + 2) * 64,
                         sb + AT_STAGE0 + (t & 1) * AT_STAGEB, tid);
            CP_COMMIT();
        }
    }

    // ---- epilogue: normalize, split fp16 hi/lo, write merged [B*S, HID]
    const float inv0 = 1.f / l0, inv1 = 1.f / l1;
    const int b = bh >> 4, h = bh & 15;
    const size_t r0 = (size_t)b * SEQ + s0 + wm + g;
    const size_t r1 = r0 + 8;
#pragma unroll
    for (int nf = 0; nf < 16; ++nf) {
        const int col = h * HD + nf * 8 + t4 * 2;
        uint32_t hi, lo;
        split_pack_h(o[nf][0] * inv0, o[nf][1] * inv0, hi, lo);
        *(uint32_t*)(Ohi + r0 * HID + col) = hi;
        *(uint32_t*)(Olo + r0 * HID + col) = lo;
        split_pack_h(o[nf][2] * inv1, o[nf][3] * inv1, hi, lo);
        *(uint32_t*)(Ohi + r1 * HID + col) = hi;
        *(uint32_t*)(Olo + r1 * HID + col) = lo;
    }
}

// ---------------------------------------------------------------------------
extern "C" void kernel_launch(void* const* d_in, const int* in_sizes, int n_in,
                              void* d_out, int out_size) {
    const float* X  = (const float*)d_in[0];
    const float* Wq = (const float*)d_in[1];
    const float* bq = (const float*)d_in[2];
    const float* Wk = (const float*)d_in[3];
    const float* bk = (const float*)d_in[4];
    const float* Wv = (const float*)d_in[5];
    const float* bv = (const float*)d_in[6];
    const float* Wo = (const float*)d_in[7];
    const float* bo = (const float*)d_in[8];
    float* out = (float*)d_out;

    __half *xhi, *xlo, *qhi, *qlo, *k16, *vt16, *ahi, *alo, *w16;
    cudaGetSymbolAddress((void**)&xhi, g_xhi);
    cudaGetSymbolAddress((void**)&xlo, g_xlo);
    cudaGetSymbolAddress((void**)&qhi, g_qhi);
    cudaGetSymbolAddress((void**)&qlo, g_qlo);
    cudaGetSymbolAddress((void**)&k16, g_k16);
    cudaGetSymbolAddress((void**)&vt16, g_vt16);
    cudaGetSymbolAddress((void**)&ahi, g_ahi);
    cudaGetSymbolAddress((void**)&alo, g_alo);
    cudaGetSymbolAddress((void**)&w16, g_w16);

    cudaFuncSetAttribute(gemm_f16x2_kernel,
                         cudaFuncAttributeMaxDynamicSharedMemorySize, GEMM_SMEM_BYTES);
    cudaFuncSetAttribute(attn_mma_kernel,
                         cudaFuncAttributeMaxDynamicSharedMemorySize, ATTN_SMEM);

    const size_t WSZ = (size_t)HID * HID;
    const int n4 = MTOT * HID / 4;
    const dim3 blk(256);

    // X -> fp16 hi/lo; all 4 weights -> fp16 [N,K] in one launch
    convert_hilo_kernel<<<dim3(n4 / 256), blk>>>(X, xhi, xlo, n4);
    convert_w4_kernel<<<dim3(HID / 64, HID / 64, 4), blk>>>(Wq, Wk, Wv, Wo, w16);

    // Fused Q/K/V projections: one launch, z selects output head-split target
    gemm_f16x2_kernel<<<dim3(HID / BN, MTOT / BM, 3), blk, GEMM_SMEM_BYTES>>>(
        xhi, xlo, w16 + 0 * WSZ, w16 + 1 * WSZ, w16 + 2 * WSZ,
        bq, bk, bv, nullptr, qhi, qlo, k16, vt16, 1);

    // Attention: 4-warp CTAs, 64 Q rows, 2 CTAs/SM
    attn_mma_kernel<<<dim3(SEQ / 64, BATCH * NHEADS), dim3(128), ATTN_SMEM>>>(
        qhi, qlo, k16, vt16, ahi, alo);

    // Output projection -> fp32 d_out
    gemm_f16x2_kernel<<<dim3(HID / BN, MTOT / BM, 1), blk, GEMM_SMEM_BYTES>>>(
        ahi, alo, w16 + 3 * WSZ, nullptr, nullptr,
        bo, nullptr, nullptr, out, nullptr, nullptr, nullptr, nullptr, 0);
}

// round 16
// speedup vs baseline: 9.5672x; 1.6018x over previous
#include <cuda_runtime.h>
#include <cuda_fp16.h>
#include <cstdint>

#define HID    2048
#define NHEADS 16
#define HD     128
#define BATCH  2
#define SEQ    2048
#define MTOT   (BATCH * SEQ)   // 4096

// ---------------------------------------------------------------------------
// Scratch (static device arrays; no cudaMalloc anywhere)
// ---------------------------------------------------------------------------
__device__ __half g_x16[(size_t)MTOT * HID];
__device__ __half g_q16[(size_t)MTOT * HID];
__device__ __half g_k16[(size_t)MTOT * HID];
__device__ __half g_vt16[(size_t)MTOT * HID];   // [b,h,d,s]
__device__ __half g_a16[(size_t)MTOT * HID];    // attention out, merged heads
__device__ __half g_w16[4][(size_t)HID * HID];  // [N][K] transposed fp16

// ---------------------------------------------------------------------------
// PTX helpers — base-target-safe only (no tcgen05 at compute_103)
// ---------------------------------------------------------------------------
static __device__ __forceinline__ uint32_t smem_u32(const void* p) {
    return (uint32_t)__cvta_generic_to_shared(p);
}

#define CP_ASYNC16(dst, src) \
    asm volatile("cp.async.cg.shared.global [%0], [%1], 16;" \
        :: "r"(dst), "l"(src) : "memory")
#define CP_COMMIT() asm volatile("cp.async.commit_group;" ::: "memory")
#define CP_WAIT_1() asm volatile("cp.async.wait_group 1;" ::: "memory")
#define CP_WAIT_0() asm volatile("cp.async.wait_group 0;" ::: "memory")

#define LDSM_X4(r0, r1, r2, r3, addr) \
    asm volatile("ldmatrix.sync.aligned.m8n8.x4.shared.b16 {%0,%1,%2,%3}, [%4];" \
        : "=r"(r0), "=r"(r1), "=r"(r2), "=r"(r3) : "r"(addr))

// mma m16n8k16 row.col fp16 -> f32
#define MMA_F16(c, a, b0, b1) \
    asm volatile("mma.sync.aligned.m16n8k16.row.col.f32.f16.f16.f32 " \
        "{%0,%1,%2,%3}, {%4,%5,%6,%7}, {%8,%9}, {%0,%1,%2,%3};" \
        : "+f"((c)[0]), "+f"((c)[1]), "+f"((c)[2]), "+f"((c)[3]) \
        : "r"((a)[0]), "r"((a)[1]), "r"((a)[2]), "r"((a)[3]), "r"(b0), "r"(b1))

// fast 2^y on the FMA pipe (avoids MUFU throughput ceiling)
static __device__ __forceinline__ float fast_exp2(float y) {
    y = fmaxf(y, -80.f);
    float fl = floorf(y);
    float f = y - fl;
    float p = 0.0013333558f;
    p = fmaf(p, f, 0.0096181291f);
    p = fmaf(p, f, 0.0555041087f);
    p = fmaf(p, f, 0.2402265070f);
    p = fmaf(p, f, 0.6931471806f);
    p = fmaf(p, f, 1.0f);
    int i = (int)fl;
    return p * __int_as_float((i + 127) << 23);
}

static __device__ __forceinline__ uint32_t pack_h(float v0, float v1) {
    __half2 h = __floats2half2_rn(v0, v1);
    return *(const uint32_t*)&h;
}

// ---------------------------------------------------------------------------
// Convert: fp32 -> fp16, elementwise (for X)
// ---------------------------------------------------------------------------
__global__ __launch_bounds__(256) void convert_x_kernel(
    const float* __restrict__ X, __half* __restrict__ x16, int n4)
{
    int i = blockIdx.x * blockDim.x + threadIdx.x;
    if (i >= n4) return;
    float4 v = ((const float4*)X)[i];
    __align__(8) __half h[4];
    h[0] = __float2half_rn(v.x); h[1] = __float2half_rn(v.y);
    h[2] = __float2half_rn(v.z); h[3] = __float2half_rn(v.w);
    ((uint2*)x16)[i] = *(const uint2*)h;
}

// ---------------------------------------------------------------------------
// Convert + transpose, 4 weights in one launch: W fp32 [K,N] -> fp16 [N,K]
// ---------------------------------------------------------------------------
__global__ __launch_bounds__(256) void convert_w4_kernel(
    const float* __restrict__ W0, const float* __restrict__ W1,
    const float* __restrict__ W2, const float* __restrict__ W3,
    __half* __restrict__ w16)
{
    __shared__ float sm[64][65];
    const int k0 = blockIdx.y * 64, n0 = blockIdx.x * 64;
    const int z = blockIdx.z;
    const int tid = threadIdx.x;
    const float* W = (z == 0) ? W0 : (z == 1) ? W1 : (z == 2) ? W2 : W3;
    __half* dst = w16 + (size_t)z * HID * HID;

#pragma unroll
    for (int i = 0; i < 4; ++i) {
        int id = tid + i * 256;
        int r = id >> 4, g = id & 15;
        float4 v = *(const float4*)(W + (size_t)(k0 + r) * HID + n0 + g * 4);
        sm[r][g * 4 + 0] = v.x; sm[r][g * 4 + 1] = v.y;
        sm[r][g * 4 + 2] = v.z; sm[r][g * 4 + 3] = v.w;
    }
    __syncthreads();
#pragma unroll
    for (int i = 0; i < 4; ++i) {
        int id = tid + i * 256;
        int r = id >> 4, g = id & 15;
        __align__(8) __half h[4];
#pragma unroll
        for (int j = 0; j < 4; ++j)
            h[j] = __float2half_rn(sm[g * 4 + j][r]);
        *(uint2*)(dst + (size_t)(n0 + r) * HID + k0 + g * 4) = *(const uint2*)h;
    }
}

// ---------------------------------------------------------------------------
// Single-pass fp16 tensor-core GEMM: C[4096,2048] = A @ B^T + bias
// fused==1 (grid.z==3): z=0 -> Q fp16 head-split [b,h,s,d]
//                       z=1 -> K fp16 head-split [b,h,s,d]
//                       z=2 -> V fp16 TRANSPOSED [b,h,d,s]
// fused==0: fp32 [M,HID] out.
// BK=64, cp.async double-buffered, 2 CTAs/SM (37KB stage, <=128 regs).
// ---------------------------------------------------------------------------
#define BM 128
#define BN 128
#define BK 64
#define KT (HID / BK)          // 32
#define ROWB 144               // 64 fp16 = 128B + 16B pad (conflict-free LDSM)
#define TILE_B (128 * ROWB)    // 18432
#define STAGE_B (2 * TILE_B)   // 36864: A, B
#define GEMM_SMEM_BYTES (2 * STAGE_B)  // 73728

static __device__ __forceinline__ void load_stage(
    const __half* __restrict__ A16, const __half* __restrict__ B16,
    int bm, int bn, int k0, uint32_t s_base, int tid)
{
#pragma unroll
    for (int mat = 0; mat < 2; ++mat) {
        const __half* base = (mat == 0 ? A16 : B16);
        const int gbase = (mat == 0 ? bm : bn);
#pragma unroll
        for (int i = 0; i < 4; ++i) {
            const int idx = tid + i * 256;     // 0..1023
            const int row = idx >> 3;          // 0..127
            const int ch  = idx & 7;           // 16B chunk (8 per 128B row)
            const __half* src = base + (size_t)(gbase + row) * HID + k0 + ch * 8;
            const uint32_t dst = s_base + mat * TILE_B + row * ROWB + ch * 16;
            CP_ASYNC16(dst, src);
        }
    }
}

__global__ __launch_bounds__(256, 2) void gemm_f16_kernel(
    const __half* __restrict__ A16,
    const __half* __restrict__ B0, const __half* __restrict__ B1,
    const __half* __restrict__ B2,
    const float* __restrict__ bias0, const float* __restrict__ bias1,
    const float* __restrict__ bias2,
    float* __restrict__ Cf,
    __half* __restrict__ Q16, __half* __restrict__ K16,
    __half* __restrict__ Vt16, int fused)
{
    extern __shared__ char smc[];
    const uint32_t s_base = smem_u32(smc);
    const int tid  = threadIdx.x;
    const int wid  = tid >> 5, lane = tid & 31;
    const int wm   = wid & 1, wn = wid >> 1;
    const int m_base = wm * 64, n_base = wn * 32;
    const int bm = blockIdx.y * BM, bn = blockIdx.x * BN;
    const int z = blockIdx.z;
    const __half* B16 = (z == 0) ? B0 : (z == 1) ? B1 : B2;
    const float* bias = (z == 0) ? bias0 : (z == 1) ? bias1 : bias2;

    float c[4][4][4];
#pragma unroll
    for (int i = 0; i < 4; ++i)
#pragma unroll
        for (int j = 0; j < 4; ++j)
#pragma unroll
            for (int r = 0; r < 4; ++r) c[i][j][r] = 0.f;

    const int a_r = lane & 15;
    const int a_c = (lane & 16) ? 8 : 0;
    const int b_r = (lane & 7) + ((lane & 16) ? 8 : 0);
    const int b_c = (lane & 8) ? 8 : 0;

    load_stage(A16, B16, bm, bn, 0, s_base, tid);
    CP_COMMIT();

    for (int t = 0; t < KT; ++t) {
        if (t + 1 < KT) {
            load_stage(A16, B16, bm, bn, (t + 1) * BK,
                       s_base + ((t + 1) & 1) * STAGE_B, tid);
            CP_COMMIT();
            CP_WAIT_1();
        } else {
            CP_WAIT_0();
        }
        __syncthreads();

        const uint32_t sb = s_base + (t & 1) * STAGE_B;
        const uint32_t sA = sb;
        const uint32_t sB = sb + TILE_B;

#pragma unroll
        for (int ks = 0; ks < 4; ++ks) {
            const int kofs = ks * 16;
            uint32_t ah[4][4], bh[2][4];
#pragma unroll
            for (int mf = 0; mf < 4; ++mf) {
                const uint32_t ra = (uint32_t)((m_base + mf * 16 + a_r) * ROWB
                                               + (kofs + a_c) * 2);
                LDSM_X4(ah[mf][0], ah[mf][1], ah[mf][2], ah[mf][3], sA + ra);
            }
#pragma unroll
            for (int nb = 0; nb < 2; ++nb) {
                const uint32_t rb = (uint32_t)((n_base + nb * 16 + b_r) * ROWB
                                               + (kofs + b_c) * 2);
                LDSM_X4(bh[nb][0], bh[nb][1], bh[nb][2], bh[nb][3], sB + rb);
            }
#pragma unroll
            for (int mf = 0; mf < 4; ++mf)
#pragma unroll
                for (int nf = 0; nf < 4; ++nf) {
                    const int nb = nf >> 1, sel = (nf & 1) * 2;
                    MMA_F16(c[mf][nf], ah[mf], bh[nb][sel], bh[nb][sel + 1]);
                }
        }
        __syncthreads();
    }

    const int g = lane >> 2, t4 = lane & 3;
#pragma unroll
    for (int mf = 0; mf < 4; ++mf) {
#pragma unroll
        for (int nf = 0; nf < 4; ++nf) {
            const int cb = bn + n_base + nf * 8 + t4 * 2;
            const float bv0 = bias[cb], bv1 = bias[cb + 1];
#pragma unroll
            for (int half = 0; half < 2; ++half) {
                const int row = bm + m_base + mf * 16 + g + half * 8;
                const float v0 = c[mf][nf][half * 2 + 0] + bv0;
                const float v1 = c[mf][nf][half * 2 + 1] + bv1;
                if (!fused) {
                    float2 v; v.x = v0; v.y = v1;
                    *(float2*)(Cf + (size_t)row * HID + cb) = v;
                } else {
                    const int b = row >> 11, s = row & 2047;
                    const int h = cb >> 7, d = cb & 127;
                    if (z == 2) {
                        // V transposed: [b,h,d,s]
                        const size_t tb = ((size_t)(b * NHEADS + h)) * HD;
                        Vt16[(tb + d) * SEQ + s]     = __float2half_rn(v0);
                        Vt16[(tb + d + 1) * SEQ + s] = __float2half_rn(v1);
                    } else {
                        __half* dst = (z == 0) ? Q16 : K16;
                        const size_t off = (((size_t)(b * NHEADS + h)) * SEQ + s) * HD + d;
                        *(uint32_t*)(dst + off) = pack_h(v0, v1);
                    }
                }
            }
        }
    }
}

// ---------------------------------------------------------------------------
// Flash attention, single-pass fp16 mma.sync, online softmax (log2 domain)
// CTA: 4 warps, 64 Q rows x one (b,h); 89KB smem -> 2 CTAs/SM.
// KV chunks of 64, cp.async double-buffered.
// ---------------------------------------------------------------------------
#define AT_QROW 272
#define AT_KROW 272
#define AT_VROW 144
#define AT_Q 0
#define AT_STAGE0 17408         // 64 * 272
#define AT_K 0
#define AT_V 17408
#define AT_STAGEB 35840         // K 17408 + V 18432
#define ATTN_SMEM (AT_STAGE0 + 2 * AT_STAGEB)   // 89088

static __device__ __forceinline__ void attn_load_kv(
    const __half* __restrict__ K16, const __half* __restrict__ Vt16,
    size_t hbase, size_t vbase, int kv0, uint32_t stage, int tid)
{
#pragma unroll
    for (int i = 0; i < 8; ++i) {
        const int idx = tid + i * 128;         // 0..1023
        const int r  = idx >> 4, ch = idx & 15;
        CP_ASYNC16(stage + AT_K + r * AT_KROW + ch * 16,
                   K16 + hbase + (size_t)(kv0 + r) * HD + ch * 8);
        const int vr = idx >> 3, vch = idx & 7;
        CP_ASYNC16(stage + AT_V + vr * AT_VROW + vch * 16,
                   Vt16 + vbase + (size_t)vr * SEQ + kv0 + vch * 8);
    }
}

__global__ __launch_bounds__(128, 2) void attn_mma_kernel(
    const __half* __restrict__ Q16, const __half* __restrict__ K16,
    const __half* __restrict__ Vt16, __half* __restrict__ O16)
{
    extern __shared__ char smc[];
    const uint32_t sb = smem_u32(smc);
    const int tid = threadIdx.x, wid = tid >> 5, lane = tid & 31;
    const int bh = blockIdx.y, qt = blockIdx.x;
    const int g = lane >> 2, t4 = lane & 3;
    const int wm = wid * 16;
    const float CSCL = 0.12751743f;   // (1/sqrt(128)) * log2(e)

    const size_t hbase = (size_t)bh * SEQ * HD;
    const size_t vbase = (size_t)bh * HD * SEQ;
    const int s0 = qt * 64;

    // Q tile (persistent in smem): 64 rows x 16 chunks
#pragma unroll
    for (int i = 0; i < 8; ++i) {
        const int idx = tid + i * 128;
        const int r = idx >> 4, ch = idx & 15;
        CP_ASYNC16(sb + AT_Q + r * AT_QROW + ch * 16,
                   Q16 + hbase + (size_t)(s0 + r) * HD + ch * 8);
    }
    attn_load_kv(K16, Vt16, hbase, vbase, 0, sb + AT_STAGE0, tid);
    CP_COMMIT();
    attn_load_kv(K16, Vt16, hbase, vbase, 64, sb + AT_STAGE0 + AT_STAGEB, tid);
    CP_COMMIT();

    float o[16][4];
#pragma unroll
    for (int nf = 0; nf < 16; ++nf)
#pragma unroll
        for (int r = 0; r < 4; ++r) o[nf][r] = 0.f;
    float m0 = -1e30f, m1 = -1e30f, l0 = 0.f, l1 = 0.f;

    const int a_r = lane & 15;
    const int a_c = (lane & 16) ? 8 : 0;
    const int b_r = (lane & 7) + ((lane & 16) ? 8 : 0);
    const int b_c = (lane & 8) ? 8 : 0;

    for (int t = 0; t < SEQ / 64; ++t) {
        if (t < SEQ / 64 - 1) { CP_WAIT_1(); } else { CP_WAIT_0(); }
        __syncthreads();
        const uint32_t st = sb + AT_STAGE0 + (t & 1) * AT_STAGEB;

        // ---- scores = Q K^T (single pass)
        float sc[8][4];
#pragma unroll
        for (int nf = 0; nf < 8; ++nf)
#pragma unroll
            for (int r = 0; r < 4; ++r) sc[nf][r] = 0.f;

#pragma unroll
        for (int kb = 0; kb < 8; ++kb) {
            uint32_t qh[4];
            const uint32_t qa = sb + AT_Q + (wm + a_r) * AT_QROW + (kb * 16 + a_c) * 2;
            LDSM_X4(qh[0], qh[1], qh[2], qh[3], qa);
#pragma unroll
            for (int nb = 0; nb < 4; ++nb) {
                uint32_t kh[4];
                const uint32_t ka = st + AT_K + (nb * 16 + b_r) * AT_KROW
                                    + (kb * 16 + b_c) * 2;
                LDSM_X4(kh[0], kh[1], kh[2], kh[3], ka);
                MMA_F16(sc[2 * nb],     qh, kh[0], kh[1]);
                MMA_F16(sc[2 * nb + 1], qh, kh[2], kh[3]);
            }
        }

        // ---- online softmax (base-2)
        float mx0 = -1e30f, mx1 = -1e30f;
#pragma unroll
        for (int nf = 0; nf < 8; ++nf) {
            sc[nf][0] *= CSCL; sc[nf][1] *= CSCL;
            sc[nf][2] *= CSCL; sc[nf][3] *= CSCL;
            mx0 = fmaxf(mx0, fmaxf(sc[nf][0], sc[nf][1]));
            mx1 = fmaxf(mx1, fmaxf(sc[nf][2], sc[nf][3]));
        }
        mx0 = fmaxf(mx0, __shfl_xor_sync(0xffffffffu, mx0, 1));
        mx0 = fmaxf(mx0, __shfl_xor_sync(0xffffffffu, mx0, 2));
        mx1 = fmaxf(mx1, __shfl_xor_sync(0xffffffffu, mx1, 1));
        mx1 = fmaxf(mx1, __shfl_xor_sync(0xffffffffu, mx1, 2));
        const float mn0 = fmaxf(m0, mx0), mn1 = fmaxf(m1, mx1);
        const float cr0 = fast_exp2(m0 - mn0), cr1 = fast_exp2(m1 - mn1);
        m0 = mn0; m1 = mn1;
        float rs0 = 0.f, rs1 = 0.f;
#pragma unroll
        for (int nf = 0; nf < 8; ++nf) {
            sc[nf][0] = fast_exp2(sc[nf][0] - mn0);
            sc[nf][1] = fast_exp2(sc[nf][1] - mn0);
            sc[nf][2] = fast_exp2(sc[nf][2] - mn1);
            sc[nf][3] = fast_exp2(sc[nf][3] - mn1);
            rs0 += sc[nf][0] + sc[nf][1];
            rs1 += sc[nf][2] + sc[nf][3];
        }
        rs0 += __shfl_xor_sync(0xffffffffu, rs0, 1);
        rs0 += __shfl_xor_sync(0xffffffffu, rs0, 2);
        rs1 += __shfl_xor_sync(0xffffffffu, rs1, 1);
        rs1 += __shfl_xor_sync(0xffffffffu, rs1, 2);
        l0 = l0 * cr0 + rs0;
        l1 = l1 * cr1 + rs1;
#pragma unroll
        for (int nf = 0; nf < 16; ++nf) {
            o[nf][0] *= cr0; o[nf][1] *= cr0;
            o[nf][2] *= cr1; o[nf][3] *= cr1;
        }

        // ---- O += P V (P packed single fp16; V^T single fp16)
#pragma unroll
        for (int kb = 0; kb < 4; ++kb) {
            uint32_t pah[4];
#pragma unroll
            for (int jj = 0; jj < 2; ++jj) {
                const int j = 2 * kb + jj;
                pah[2 * jj]     = pack_h(sc[j][0], sc[j][1]);
                pah[2 * jj + 1] = pack_h(sc[j][2], sc[j][3]);
            }
#pragma unroll
            for (int nb = 0; nb < 8; ++nb) {
                uint32_t vh[4];
                const uint32_t va = st + AT_V + (nb * 16 + b_r) * AT_VROW
                                    + (kb * 16 + b_c) * 2;
                LDSM_X4(vh[0], vh[1], vh[2], vh[3], va);
                MMA_F16(o[2 * nb],     pah, vh[0], vh[1]);
                MMA_F16(o[2 * nb + 1], pah, vh[2], vh[3]);
            }
        }
        __syncthreads();
        if (t + 2 < SEQ / 64) {
            attn_load_kv(K16, Vt16, hbase, vbase, (t + 2) * 64,
                         sb + AT_STAGE0 + (t & 1) * AT_STAGEB, tid);
            CP_COMMIT();
        }
    }

    // ---- epilogue: normalize, fp16, write merged [B*S, HID]
    const float inv0 = 1.f / l0, inv1 = 1.f / l1;
    const int b = bh >> 4, h = bh & 15;
    const size_t r0 = (size_t)b * SEQ + s0 + wm + g;
    const size_t r1 = r0 + 8;
#pragma unroll
    for (int nf = 0; nf < 16; ++nf) {
        const int col = h * HD + nf * 8 + t4 * 2;
        *(uint32_t*)(O16 + r0 * HID + col) = pack_h(o[nf][0] * inv0, o[nf][1] * inv0);
        *(uint32_t*)(O16 + r1 * HID + col) = pack_h(o[nf][2] * inv1, o[nf][3] * inv1);
    }
}

// ---------------------------------------------------------------------------
extern "C" void kernel_launch(void* const* d_in, const int* in_sizes, int n_in,
                              void* d_out, int out_size) {
    const float* X  = (const float*)d_in[0];
    const float* Wq = (const float*)d_in[1];
    const float* bq = (const float*)d_in[2];
    const float* Wk = (const float*)d_in[3];
    const float* bk = (const float*)d_in[4];
    const float* Wv = (const float*)d_in[5];
    const float* bv = (const float*)d_in[6];
    const float* Wo = (const float*)d_in[7];
    const float* bo = (const float*)d_in[8];
    float* out = (float*)d_out;

    __half *x16, *q16, *k16, *vt16, *a16, *w16;
    cudaGetSymbolAddress((void**)&x16, g_x16);
    cudaGetSymbolAddress((void**)&q16, g_q16);
    cudaGetSymbolAddress((void**)&k16, g_k16);
    cudaGetSymbolAddress((void**)&vt16, g_vt16);
    cudaGetSymbolAddress((void**)&a16, g_a16);
    cudaGetSymbolAddress((void**)&w16, g_w16);

    cudaFuncSetAttribute(gemm_f16_kernel,
                         cudaFuncAttributeMaxDynamicSharedMemorySize, GEMM_SMEM_BYTES);
    cudaFuncSetAttribute(attn_mma_kernel,
                         cudaFuncAttributeMaxDynamicSharedMemorySize, ATTN_SMEM);

    const size_t WSZ = (size_t)HID * HID;
    const int n4 = MTOT * HID / 4;
    const dim3 blk(256);

    // X -> fp16; all 4 weights -> fp16 [N,K] in one launch
    convert_x_kernel<<<dim3(n4 / 256), blk>>>(X, x16, n4);
    convert_w4_kernel<<<dim3(HID / 64, HID / 64, 4), blk>>>(Wq, Wk, Wv, Wo, w16);

    // Fused Q/K/V projections: one launch, z selects output head-split target
    gemm_f16_kernel<<<dim3(HID / BN, MTOT / BM, 3), blk, GEMM_SMEM_BYTES>>>(
        x16, w16 + 0 * WSZ, w16 + 1 * WSZ, w16 + 2 * WSZ,
        bq, bk, bv, nullptr, q16, k16, vt16, 1);

    // Attention: 4-warp CTAs, 64 Q rows, 2 CTAs/SM
    attn_mma_kernel<<<dim3(SEQ / 64, BATCH * NHEADS), dim3(128), ATTN_SMEM>>>(
        q16, k16, vt16, a16);

    // Output projection -> fp32 d_out
    gemm_f16_kernel<<<dim3(HID / BN, MTOT / BM, 1), blk, GEMM_SMEM_BYTES>>>(
        a16, w16 + 3 * WSZ, nullptr, nullptr,
        bo, nullptr, nullptr, out, nullptr, nullptr, nullptr, 0);
}

// round 17
// speedup vs baseline: 9.6582x; 1.0095x over previous
#include <cuda_runtime.h>
#include <cuda_fp16.h>
#include <cstdint>

#define HID    2048
#define NHEADS 16
#define HD     128
#define BATCH  2
#define SEQ    2048
#define MTOT   (BATCH * SEQ)   // 4096

// ---------------------------------------------------------------------------
// Scratch (static device arrays; no cudaMalloc anywhere)
// ---------------------------------------------------------------------------
__device__ __half g_x16[(size_t)MTOT * HID];
__device__ __half g_q16[(size_t)MTOT * HID];
__device__ __half g_k16[(size_t)MTOT * HID];
__device__ __half g_vt16[(size_t)MTOT * HID];   // [b,h,d,s]
__device__ __half g_a16[(size_t)MTOT * HID];    // attention out, merged heads
__device__ __half g_w16[4][(size_t)HID * HID];  // [N][K] transposed fp16

// ---------------------------------------------------------------------------
// PTX helpers — base-target-safe only (no tcgen05 at compute_103)
// ---------------------------------------------------------------------------
static __device__ __forceinline__ uint32_t smem_u32(const void* p) {
    return (uint32_t)__cvta_generic_to_shared(p);
}

#define CP_ASYNC16(dst, src) \
    asm volatile("cp.async.cg.shared.global [%0], [%1], 16;" \
        :: "r"(dst), "l"(src) : "memory")
#define CP_COMMIT() asm volatile("cp.async.commit_group;" ::: "memory")
#define CP_WAIT_2() asm volatile("cp.async.wait_group 2;" ::: "memory")
#define CP_WAIT_1() asm volatile("cp.async.wait_group 1;" ::: "memory")
#define CP_WAIT_0() asm volatile("cp.async.wait_group 0;" ::: "memory")

#define LDSM_X4(r0, r1, r2, r3, addr) \
    asm volatile("ldmatrix.sync.aligned.m8n8.x4.shared.b16 {%0,%1,%2,%3}, [%4];" \
        : "=r"(r0), "=r"(r1), "=r"(r2), "=r"(r3) : "r"(addr))

// mma m16n8k16 row.col fp16 -> f32
#define MMA_F16(c, a, b0, b1) \
    asm volatile("mma.sync.aligned.m16n8k16.row.col.f32.f16.f16.f32 " \
        "{%0,%1,%2,%3}, {%4,%5,%6,%7}, {%8,%9}, {%0,%1,%2,%3};" \
        : "+f"((c)[0]), "+f"((c)[1]), "+f"((c)[2]), "+f"((c)[3]) \
        : "r"((a)[0]), "r"((a)[1]), "r"((a)[2]), "r"((a)[3]), "r"(b0), "r"(b1))

// fast 2^y on the FMA pipe (avoids MUFU throughput ceiling)
static __device__ __forceinline__ float fast_exp2(float y) {
    y = fmaxf(y, -80.f);
    float fl = floorf(y);
    float f = y - fl;
    float p = 0.0013333558f;
    p = fmaf(p, f, 0.0096181291f);
    p = fmaf(p, f, 0.0555041087f);
    p = fmaf(p, f, 0.2402265070f);
    p = fmaf(p, f, 0.6931471806f);
    p = fmaf(p, f, 1.0f);
    int i = (int)fl;
    return p * __int_as_float((i + 127) << 23);
}

static __device__ __forceinline__ uint32_t pack_h(float v0, float v1) {
    __half2 h = __floats2half2_rn(v0, v1);
    return *(const uint32_t*)&h;
}

// ---------------------------------------------------------------------------
// Convert: fp32 -> fp16, elementwise (for X)
// ---------------------------------------------------------------------------
__global__ __launch_bounds__(256) void convert_x_kernel(
    const float* __restrict__ X, __half* __restrict__ x16, int n4)
{
    int i = blockIdx.x * blockDim.x + threadIdx.x;
    if (i >= n4) return;
    float4 v = ((const float4*)X)[i];
    __align__(8) __half h[4];
    h[0] = __float2half_rn(v.x); h[1] = __float2half_rn(v.y);
    h[2] = __float2half_rn(v.z); h[3] = __float2half_rn(v.w);
    ((uint2*)x16)[i] = *(const uint2*)h;
}

// ---------------------------------------------------------------------------
// Convert + transpose, 4 weights in one launch: W fp32 [K,N] -> fp16 [N,K]
// ---------------------------------------------------------------------------
__global__ __launch_bounds__(256) void convert_w4_kernel(
    const float* __restrict__ W0, const float* __restrict__ W1,
    const float* __restrict__ W2, const float* __restrict__ W3,
    __half* __restrict__ w16)
{
    __shared__ float sm[64][65];
    const int k0 = blockIdx.y * 64, n0 = blockIdx.x * 64;
    const int z = blockIdx.z;
    const int tid = threadIdx.x;
    const float* W = (z == 0) ? W0 : (z == 1) ? W1 : (z == 2) ? W2 : W3;
    __half* dst = w16 + (size_t)z * HID * HID;

#pragma unroll
    for (int i = 0; i < 4; ++i) {
        int id = tid + i * 256;
        int r = id >> 4, g = id & 15;
        float4 v = *(const float4*)(W + (size_t)(k0 + r) * HID + n0 + g * 4);
        sm[r][g * 4 + 0] = v.x; sm[r][g * 4 + 1] = v.y;
        sm[r][g * 4 + 2] = v.z; sm[r][g * 4 + 3] = v.w;
    }
    __syncthreads();
#pragma unroll
    for (int i = 0; i < 4; ++i) {
        int id = tid + i * 256;
        int r = id >> 4, g = id & 15;
        __align__(8) __half h[4];
#pragma unroll
        for (int j = 0; j < 4; ++j)
            h[j] = __float2half_rn(sm[g * 4 + j][r]);
        *(uint2*)(dst + (size_t)(n0 + r) * HID + k0 + g * 4) = *(const uint2*)h;
    }
}

// ---------------------------------------------------------------------------
// Single-pass fp16 tensor-core GEMM: C[4096,2048] = A @ B^T + bias
// fused==1 (grid.z==3): z=0 -> Q fp16 head-split; z=1 -> K fp16; z=2 -> V^T
// fused==0: fp32 [M,HID] out.
// BK=64, cp.async 3-stage pipeline, 2 CTAs/SM.
// ---------------------------------------------------------------------------
#define BM 128
#define BN 128
#define BK 64
#define KT (HID / BK)          // 32
#define ROWB 144               // 64 fp16 = 128B + 16B pad (conflict-free LDSM)
#define TILE_B (128 * ROWB)    // 18432
#define STAGE_B (2 * TILE_B)   // 36864: A, B
#define GEMM_STAGES 3
#define GEMM_SMEM_BYTES (GEMM_STAGES * STAGE_B)  // 110592

static __device__ __forceinline__ void load_stage(
    const __half* __restrict__ A16, const __half* __restrict__ B16,
    int bm, int bn, int k0, uint32_t s_base, int tid)
{
#pragma unroll
    for (int mat = 0; mat < 2; ++mat) {
        const __half* base = (mat == 0 ? A16 : B16);
        const int gbase = (mat == 0 ? bm : bn);
#pragma unroll
        for (int i = 0; i < 4; ++i) {
            const int idx = tid + i * 256;     // 0..1023
            const int row = idx >> 3;          // 0..127
            const int ch  = idx & 7;           // 16B chunk (8 per 128B row)
            const __half* src = base + (size_t)(gbase + row) * HID + k0 + ch * 8;
            const uint32_t dst = s_base + mat * TILE_B + row * ROWB + ch * 16;
            CP_ASYNC16(dst, src);
        }
    }
}

__global__ __launch_bounds__(256, 2) void gemm_f16_kernel(
    const __half* __restrict__ A16,
    const __half* __restrict__ B0, const __half* __restrict__ B1,
    const __half* __restrict__ B2,
    const float* __restrict__ bias0, const float* __restrict__ bias1,
    const float* __restrict__ bias2,
    float* __restrict__ Cf,
    __half* __restrict__ Q16, __half* __restrict__ K16,
    __half* __restrict__ Vt16, int fused)
{
    extern __shared__ char smc[];
    const uint32_t s_base = smem_u32(smc);
    const int tid  = threadIdx.x;
    const int wid  = tid >> 5, lane = tid & 31;
    const int wm   = wid & 1, wn = wid >> 1;
    const int m_base = wm * 64, n_base = wn * 32;
    const int bm = blockIdx.y * BM, bn = blockIdx.x * BN;
    const int z = blockIdx.z;
    const __half* B16 = (z == 0) ? B0 : (z == 1) ? B1 : B2;
    const float* bias = (z == 0) ? bias0 : (z == 1) ? bias1 : bias2;

    float c[4][4][4];
#pragma unroll
    for (int i = 0; i < 4; ++i)
#pragma unroll
        for (int j = 0; j < 4; ++j)
#pragma unroll
            for (int r = 0; r < 4; ++r) c[i][j][r] = 0.f;

    const int a_r = lane & 15;
    const int a_c = (lane & 16) ? 8 : 0;
    const int b_r = (lane & 7) + ((lane & 16) ? 8 : 0);
    const int b_c = (lane & 8) ? 8 : 0;

    load_stage(A16, B16, bm, bn, 0, s_base, tid);
    CP_COMMIT();
    load_stage(A16, B16, bm, bn, BK, s_base + STAGE_B, tid);
    CP_COMMIT();
    load_stage(A16, B16, bm, bn, 2 * BK, s_base + 2 * STAGE_B, tid);
    CP_COMMIT();

    int s_cur = 0, s_load = 0;   // compute stage, reload target
    for (int t = 0; t < KT; ++t) {
        CP_WAIT_2();
        __syncthreads();

        const uint32_t sb = s_base + s_cur * STAGE_B;
        const uint32_t sA = sb;
        const uint32_t sB = sb + TILE_B;

#pragma unroll
        for (int ks = 0; ks < 4; ++ks) {
            const int kofs = ks * 16;
            uint32_t ah[4][4], bh[2][4];
#pragma unroll
            for (int mf = 0; mf < 4; ++mf) {
                const uint32_t ra = (uint32_t)((m_base + mf * 16 + a_r) * ROWB
                                               + (kofs + a_c) * 2);
                LDSM_X4(ah[mf][0], ah[mf][1], ah[mf][2], ah[mf][3], sA + ra);
            }
#pragma unroll
            for (int nb = 0; nb < 2; ++nb) {
                const uint32_t rb = (uint32_t)((n_base + nb * 16 + b_r) * ROWB
                                               + (kofs + b_c) * 2);
                LDSM_X4(bh[nb][0], bh[nb][1], bh[nb][2], bh[nb][3], sB + rb);
            }
#pragma unroll
            for (int mf = 0; mf < 4; ++mf)
#pragma unroll
                for (int nf = 0; nf < 4; ++nf) {
                    const int nb = nf >> 1, sel = (nf & 1) * 2;
                    MMA_F16(c[mf][nf], ah[mf], bh[nb][sel], bh[nb][sel + 1]);
                }
        }
        __syncthreads();
        if (t + 3 < KT)
            load_stage(A16, B16, bm, bn, (t + 3) * BK, s_base + s_load * STAGE_B, tid);
        CP_COMMIT();   // always commit: keeps pending-group count invariant
        s_cur  = (s_cur == GEMM_STAGES - 1) ? 0 : s_cur + 1;
        s_load = (s_load == GEMM_STAGES - 1) ? 0 : s_load + 1;
    }

    const int g = lane >> 2, t4 = lane & 3;
#pragma unroll
    for (int mf = 0; mf < 4; ++mf) {
#pragma unroll
        for (int nf = 0; nf < 4; ++nf) {
            const int cb = bn + n_base + nf * 8 + t4 * 2;
            const float bv0 = bias[cb], bv1 = bias[cb + 1];
#pragma unroll
            for (int half = 0; half < 2; ++half) {
                const int row = bm + m_base + mf * 16 + g + half * 8;
                const float v0 = c[mf][nf][half * 2 + 0] + bv0;
                const float v1 = c[mf][nf][half * 2 + 1] + bv1;
                if (!fused) {
                    float2 v; v.x = v0; v.y = v1;
                    *(float2*)(Cf + (size_t)row * HID + cb) = v;
                } else {
                    const int b = row >> 11, s = row & 2047;
                    const int h = cb >> 7, d = cb & 127;
                    if (z == 2) {
                        const size_t tb = ((size_t)(b * NHEADS + h)) * HD;
                        Vt16[(tb + d) * SEQ + s]     = __float2half_rn(v0);
                        Vt16[(tb + d + 1) * SEQ + s] = __float2half_rn(v1);
                    } else {
                        __half* dst = (z == 0) ? Q16 : K16;
                        const size_t off = (((size_t)(b * NHEADS + h)) * SEQ + s) * HD + d;
                        *(uint32_t*)(dst + off) = pack_h(v0, v1);
                    }
                }
            }
        }
    }
}

// ---------------------------------------------------------------------------
// Flash attention, single-pass fp16 mma.sync, online softmax (log2 domain),
// software-pipelined: QK(t+1) issued BEFORE softmax(t)/PV(t) so the tensor
// pipe has independent work during the softmax dependency chain.
// CTA: 4 warps, 64 Q rows x one (b,h); 89KB smem -> 2 CTAs/SM.
// K and V prefetched in separate commit groups (distance 2).
// ---------------------------------------------------------------------------
#define AT_QROW 272
#define AT_KROW 272
#define AT_VROW 144
#define AT_Q    0
#define AT_KS0  17408                 // two K stages of 64*272 = 17408
#define AT_KSTB 17408
#define AT_VS0  (AT_KS0 + 2 * AT_KSTB)   // 52224; two V stages of 128*144
#define AT_VSTB 18432
#define ATTN_SMEM (AT_VS0 + 2 * AT_VSTB)   // 89088
#define NT (SEQ / 64)                 // 32

static __device__ __forceinline__ void attn_load_k(
    const __half* __restrict__ K16, size_t hbase, int kv0, uint32_t stage, int tid)
{
#pragma unroll
    for (int i = 0; i < 8; ++i) {
        const int idx = tid + i * 128;
        const int r = idx >> 4, ch = idx & 15;
        CP_ASYNC16(stage + r * AT_KROW + ch * 16,
                   K16 + hbase + (size_t)(kv0 + r) * HD + ch * 8);
    }
}

static __device__ __forceinline__ void attn_load_v(
    const __half* __restrict__ Vt16, size_t vbase, int kv0, uint32_t stage, int tid)
{
#pragma unroll
    for (int i = 0; i < 8; ++i) {
        const int idx = tid + i * 128;
        const int vr = idx >> 3, vch = idx & 7;
        CP_ASYNC16(stage + vr * AT_VROW + vch * 16,
                   Vt16 + vbase + (size_t)vr * SEQ + kv0 + vch * 8);
    }
}

__global__ __launch_bounds__(128, 2) void attn_mma_kernel(
    const __half* __restrict__ Q16, const __half* __restrict__ K16,
    const __half* __restrict__ Vt16, __half* __restrict__ O16)
{
    extern __shared__ char smc[];
    const uint32_t sb = smem_u32(smc);
    const int tid = threadIdx.x, wid = tid >> 5, lane = tid & 31;
    const int bh = blockIdx.y, qt = blockIdx.x;
    const int g = lane >> 2, t4 = lane & 3;
    const int wm = wid * 16;
    const float CSCL = 0.12751743f;   // (1/sqrt(128)) * log2(e)

    const size_t hbase = (size_t)bh * SEQ * HD;
    const size_t vbase = (size_t)bh * HD * SEQ;
    const int s0 = qt * 64;

    const int a_r = lane & 15;
    const int a_c = (lane & 16) ? 8 : 0;
    const int b_r = (lane & 7) + ((lane & 16) ? 8 : 0);
    const int b_c = (lane & 8) ? 8 : 0;

    // Prologue: Q + K0/V0 (group1), K1 (group2), V1 (group3)
#pragma unroll
    for (int i = 0; i < 8; ++i) {
        const int idx = tid + i * 128;
        const int r = idx >> 4, ch = idx & 15;
        CP_ASYNC16(sb + AT_Q + r * AT_QROW + ch * 16,
                   Q16 + hbase + (size_t)(s0 + r) * HD + ch * 8);
    }
    attn_load_k(K16, hbase, 0, sb + AT_KS0, tid);
    attn_load_v(Vt16, vbase, 0, sb + AT_VS0, tid);
    CP_COMMIT();
    attn_load_k(K16, hbase, 64, sb + AT_KS0 + AT_KSTB, tid);
    CP_COMMIT();
    attn_load_v(Vt16, vbase, 64, sb + AT_VS0 + AT_VSTB, tid);
    CP_COMMIT();

    float o[16][4];
#pragma unroll
    for (int nf = 0; nf < 16; ++nf)
#pragma unroll
        for (int r = 0; r < 4; ++r) o[nf][r] = 0.f;
    float m0 = -1e30f, m1 = -1e30f, l0 = 0.f, l1 = 0.f;
    float scA[8][4], scB[8][4];

    // QK for a given K stage -> dst
    auto qk = [&](float (&dst)[8][4], uint32_t kst) {
#pragma unroll
        for (int nf = 0; nf < 8; ++nf)
#pragma unroll
            for (int r = 0; r < 4; ++r) dst[nf][r] = 0.f;
#pragma unroll
        for (int kb = 0; kb < 8; ++kb) {
            uint32_t qh[4];
            const uint32_t qa = sb + AT_Q + (wm + a_r) * AT_QROW + (kb * 16 + a_c) * 2;
            LDSM_X4(qh[0], qh[1], qh[2], qh[3], qa);
#pragma unroll
            for (int nb = 0; nb < 4; ++nb) {
                uint32_t kh[4];
                const uint32_t ka = kst + (nb * 16 + b_r) * AT_KROW + (kb * 16 + b_c) * 2;
                LDSM_X4(kh[0], kh[1], kh[2], kh[3], ka);
                MMA_F16(dst[2 * nb],     qh, kh[0], kh[1]);
                MMA_F16(dst[2 * nb + 1], qh, kh[2], kh[3]);
            }
        }
    };

    // One pipelined iteration: softmax+PV on cur (tile t); QK(t+1) into nxt
    auto iter = [&](float (&cur)[8][4], float (&nxt)[8][4], int t) {
        CP_WAIT_1();          // K(t+1) and V(t) complete
        __syncthreads();
        // prefetch K(t+2) into the K stage freed by QK(t) (stage t&1)
        if (t + 2 < NT)
            attn_load_k(K16, hbase, (t + 2) * 64, sb + AT_KS0 + (t & 1) * AT_KSTB, tid);
        CP_COMMIT();

        // QK(t+1): independent of softmax(t) — fills the tensor pipe
        if (t + 1 < NT)
            qk(nxt, sb + AT_KS0 + ((t + 1) & 1) * AT_KSTB);

        // ---- online softmax (base-2) on cur
        float mx0 = -1e30f, mx1 = -1e30f;
#pragma unroll
        for (int nf = 0; nf < 8; ++nf) {
            cur[nf][0] *= CSCL; cur[nf][1] *= CSCL;
            cur[nf][2] *= CSCL; cur[nf][3] *= CSCL;
            mx0 = fmaxf(mx0, fmaxf(cur[nf][0], cur[nf][1]));
            mx1 = fmaxf(mx1, fmaxf(cur[nf][2], cur[nf][3]));
        }
        mx0 = fmaxf(mx0, __shfl_xor_sync(0xffffffffu, mx0, 1));
        mx0 = fmaxf(mx0, __shfl_xor_sync(0xffffffffu, mx0, 2));
        mx1 = fmaxf(mx1, __shfl_xor_sync(0xffffffffu, mx1, 1));
        mx1 = fmaxf(mx1, __shfl_xor_sync(0xffffffffu, mx1, 2));
        const float mn0 = fmaxf(m0, mx0), mn1 = fmaxf(m1, mx1);
        const float cr0 = fast_exp2(m0 - mn0), cr1 = fast_exp2(m1 - mn1);
        m0 = mn0; m1 = mn1;
        float rs0 = 0.f, rs1 = 0.f;
#pragma unroll
        for (int nf = 0; nf < 8; ++nf) {
            cur[nf][0] = fast_exp2(cur[nf][0] - mn0);
            cur[nf][1] = fast_exp2(cur[nf][1] - mn0);
            cur[nf][2] = fast_exp2(cur[nf][2] - mn1);
            cur[nf][3] = fast_exp2(cur[nf][3] - mn1);
            rs0 += cur[nf][0] + cur[nf][1];
            rs1 += cur[nf][2] + cur[nf][3];
        }
        rs0 += __shfl_xor_sync(0xffffffffu, rs0, 1);
        rs0 += __shfl_xor_sync(0xffffffffu, rs0, 2);
        rs1 += __shfl_xor_sync(0xffffffffu, rs1, 1);
        rs1 += __shfl_xor_sync(0xffffffffu, rs1, 2);
        l0 = l0 * cr0 + rs0;
        l1 = l1 * cr1 + rs1;
#pragma unroll
        for (int nf = 0; nf < 16; ++nf) {
            o[nf][0] *= cr0; o[nf][1] *= cr0;
            o[nf][2] *= cr1; o[nf][3] *= cr1;
        }

        // ---- O += P V from V stage (t&1)
        const uint32_t vst = sb + AT_VS0 + (t & 1) * AT_VSTB;
#pragma unroll
        for (int kb = 0; kb < 4; ++kb) {
            uint32_t pah[4];
#pragma unroll
            for (int jj = 0; jj < 2; ++jj) {
                const int j = 2 * kb + jj;
                pah[2 * jj]     = pack_h(cur[j][0], cur[j][1]);
                pah[2 * jj + 1] = pack_h(cur[j][2], cur[j][3]);
            }
#pragma unroll
            for (int nb = 0; nb < 8; ++nb) {
                uint32_t vh[4];
                const uint32_t va = vst + (nb * 16 + b_r) * AT_VROW + (kb * 16 + b_c) * 2;
                LDSM_X4(vh[0], vh[1], vh[2], vh[3], va);
                MMA_F16(o[2 * nb],     pah, vh[0], vh[1]);
                MMA_F16(o[2 * nb + 1], pah, vh[2], vh[3]);
            }
        }
        __syncthreads();
        // prefetch V(t+2) into the V stage just drained (stage t&1)
        if (t + 2 < NT)
            attn_load_v(Vt16, vbase, (t + 2) * 64, sb + AT_VS0 + (t & 1) * AT_VSTB, tid);
        CP_COMMIT();
    };

    // Prologue compute: QK(0)
    CP_WAIT_2();          // group1 (Q, K0, V0) complete
    __syncthreads();
    qk(scA, sb + AT_KS0);

    for (int t = 0; t < NT; t += 2) {
        iter(scA, scB, t);
        iter(scB, scA, t + 1);
    }

    // ---- epilogue: normalize, fp16, write merged [B*S, HID]
    const float inv0 = 1.f / l0, inv1 = 1.f / l1;
    const int b = bh >> 4, h = bh & 15;
    const size_t r0 = (size_t)b * SEQ + s0 + wm + g;
    const size_t r1 = r0 + 8;
#pragma unroll
    for (int nf = 0; nf < 16; ++nf) {
        const int col = h * HD + nf * 8 + t4 * 2;
        *(uint32_t*)(O16 + r0 * HID + col) = pack_h(o[nf][0] * inv0, o[nf][1] * inv0);
        *(uint32_t*)(O16 + r1 * HID + col) = pack_h(o[nf][2] * inv1, o[nf][3] * inv1);
    }
}

// ---------------------------------------------------------------------------
extern "C" void kernel_launch(void* const* d_in, const int* in_sizes, int n_in,
                              void* d_out, int out_size) {
    const float* X  = (const float*)d_in[0];
    const float* Wq = (const float*)d_in[1];
    const float* bq = (const float*)d_in[2];
    const float* Wk = (const float*)d_in[3];
    const float* bk = (const float*)d_in[4];
    const float* Wv = (const float*)d_in[5];
    const float* bv = (const float*)d_in[6];
    const float* Wo = (const float*)d_in[7];
    const float* bo = (const float*)d_in[8];
    float* out = (float*)d_out;

    __half *x16, *q16, *k16, *vt16, *a16, *w16;
    cudaGetSymbolAddress((void**)&x16, g_x16);
    cudaGetSymbolAddress((void**)&q16, g_q16);
    cudaGetSymbolAddress((void**)&k16, g_k16);
    cudaGetSymbolAddress((void**)&vt16, g_vt16);
    cudaGetSymbolAddress((void**)&a16, g_a16);
    cudaGetSymbolAddress((void**)&w16, g_w16);

    cudaFuncSetAttribute(gemm_f16_kernel,
                         cudaFuncAttributeMaxDynamicSharedMemorySize, GEMM_SMEM_BYTES);
    cudaFuncSetAttribute(attn_mma_kernel,
                         cudaFuncAttributeMaxDynamicSharedMemorySize, ATTN_SMEM);

    const size_t WSZ = (size_t)HID * HID;
    const int n4 = MTOT * HID / 4;
    const dim3 blk(256);

    // X -> fp16; all 4 weights -> fp16 [N,K] in one launch
    convert_x_kernel<<<dim3(n4 / 256), blk>>>(X, x16, n4);
    convert_w4_kernel<<<dim3(HID / 64, HID / 64, 4), blk>>>(Wq, Wk, Wv, Wo, w16);

    // Fused Q/K/V projections: one launch, z selects output head-split target
    gemm_f16_kernel<<<dim3(HID / BN, MTOT / BM, 3), blk, GEMM_SMEM_BYTES>>>(
        x16, w16 + 0 * WSZ, w16 + 1 * WSZ, w16 + 2 * WSZ,
        bq, bk, bv, nullptr, q16, k16, vt16, 1);

    // Attention: 4-warp CTAs, 64 Q rows, 2 CTAs/SM, QK(t+1)/softmax(t) overlap
    attn_mma_kernel<<<dim3(SEQ / 64, BATCH * NHEADS), dim3(128), ATTN_SMEM>>>(
        q16, k16, vt16, a16);

    // Output projection -> fp32 d_out
    gemm_f16_kernel<<<dim3(HID / BN, MTOT / BM, 1), blk, GEMM_SMEM_BYTES>>>(
        a16, w16 + 3 * WSZ, nullptr, nullptr,
        bo, nullptr, nullptr, out, nullptr, nullptr, nullptr, 0);
}